// round 1
// baseline (speedup 1.0000x reference)
#include <cuda_runtime.h>
#include <math.h>

#define NN   50000
#define E1   300000
#define EN   30000
#define ET   330000
#define OREL 12800000      // 50000*256
#define O3   12865536      // + 256*256
#define NREL 256

// ---------------- device scratch (static, allocation-free) ----------------
__device__ float g_ent[NN*128];
__device__ float g_Pd1[2*NN*128];
__device__ float g_Ps1[2*NN*128];
__device__ float g_R1 [2*NREL*128];
__device__ float g_sd1[2*NN];
__device__ float g_ss1[2*NN];
__device__ float g_sr1[2*NREL];
__device__ float g_rs1[2*NN];
__device__ float g_S1 [2*NN*128];
__device__ float g_x  [NN*256];
__device__ float g_Xd [NN*256];
__device__ float g_Xs [NN*256];
__device__ float g_R2 [NREL*256];
__device__ float g_sd2[NN];
__device__ float g_ss2[NN];
__device__ float g_sr2[NREL];
__device__ float g_rs2[NN];
__device__ float g_S2 [NN*256];
__device__ float g_eup[NN*256];
__device__ float g_mask[NN];

// ---------------- helpers ----------------
__device__ __forceinline__ float4 ld4(const float* p){ return *reinterpret_cast<const float4*>(p); }
__device__ __forceinline__ void   st4(float* p, float4 v){ *reinterpret_cast<float4*>(p) = v; }
__device__ __forceinline__ float  elu1(float x){ return x > 0.f ? x : expm1f(x); }
__device__ __forceinline__ float  wred(float v){
    #pragma unroll
    for (int o = 16; o; o >>= 1) v += __shfl_xor_sync(0xffffffffu, v, o);
    return v;
}
__device__ __forceinline__ void red4(float* p, float4 v){
    asm volatile("red.global.add.v4.f32 [%0], {%1, %2, %3, %4};"
                 :: "l"(p), "f"(v.x), "f"(v.y), "f"(v.z), "f"(v.w) : "memory");
}

// ---------------- zero fill ----------------
__global__ void k_zero(float* __restrict__ p, int n){
    int i  = blockIdx.x * blockDim.x + threadIdx.x;
    int st = gridDim.x * blockDim.x;
    for (; i < n; i += st) p[i] = 0.f;
}

// ---------------- row l2-normalize, D=128, warp/row ----------------
__global__ void k_l2norm128(const float* __restrict__ in, float* __restrict__ out){
    int n = (blockIdx.x * blockDim.x + threadIdx.x) >> 5;
    int lane = threadIdx.x & 31;
    if (n >= NN) return;
    int c = lane * 4;
    float4 v = ld4(in + (size_t)n*128 + c);
    float ss = v.x*v.x + v.y*v.y + v.z*v.z + v.w*v.w;
    ss = wred(ss);
    float s = 1.f / fmaxf(sqrtf(ss), 1e-12f);
    st4(out + (size_t)n*128 + c, make_float4(v.x*s, v.y*s, v.z*s, v.w*s));
}

// ---------------- row dot with vector, warp/row ----------------
__global__ void k_rowdot(const float* __restrict__ A, const float* __restrict__ v,
                         float* __restrict__ out, int M, int D){
    int r = (blockIdx.x * blockDim.x + threadIdx.x) >> 5;
    int lane = threadIdx.x & 31;
    if (r >= M) return;
    float acc = 0.f;
    for (int c = lane * 4; c < D; c += 128){
        float4 a = ld4(A + (size_t)r*D + c);
        float4 b = ld4(v + c);
        acc += a.x*b.x + a.y*b.y + a.z*b.z + a.w*b.w;
    }
    acc = wred(acc);
    if (lane == 0) out[r] = acc;
}

// ---------------- SGEMM: C[M,N] = A[M,K] * op(B) ----------------
// TRANSB=true : B stored [N,K] (row n contiguous over k), ldb = row stride
// TRANSB=false: B stored [K,N]
#define BM 128
#define BN 128
#define BKK 16
template<bool TRANSB>
__global__ __launch_bounds__(256)
void sgemm(const float* __restrict__ A, int lda,
           const float* __restrict__ B, int ldb,
           float* __restrict__ C, int ldc,
           int M, int N, int K)
{
    __shared__ float As[BKK][BM+4];
    __shared__ float Bs[BKK][BN+4];
    const int bm = blockIdx.y * BM;
    const int bn = blockIdx.x * BN;
    const int tid = threadIdx.x;
    const int tx = tid & 15;
    const int ty = tid >> 4;
    float acc[8][8];
    #pragma unroll
    for (int i = 0; i < 8; i++)
        #pragma unroll
        for (int j = 0; j < 8; j++) acc[i][j] = 0.f;

    for (int k0 = 0; k0 < K; k0 += BKK){
        {   // A tile: 128 rows x 16 k
            int ar = tid >> 1;
            int ak = (tid & 1) * 8;
            float4 a0 = make_float4(0,0,0,0), a1 = a0;
            if (bm + ar < M){
                const float* ap = A + (size_t)(bm + ar) * lda + k0 + ak;
                a0 = ld4(ap); a1 = ld4(ap + 4);
            }
            As[ak+0][ar]=a0.x; As[ak+1][ar]=a0.y; As[ak+2][ar]=a0.z; As[ak+3][ar]=a0.w;
            As[ak+4][ar]=a1.x; As[ak+5][ar]=a1.y; As[ak+6][ar]=a1.z; As[ak+7][ar]=a1.w;
        }
        if (TRANSB){
            int br = tid >> 1;
            int bk = (tid & 1) * 8;
            float4 b0 = make_float4(0,0,0,0), b1 = b0;
            if (bn + br < N){
                const float* bp = B + (size_t)(bn + br) * ldb + k0 + bk;
                b0 = ld4(bp); b1 = ld4(bp + 4);
            }
            Bs[bk+0][br]=b0.x; Bs[bk+1][br]=b0.y; Bs[bk+2][br]=b0.z; Bs[bk+3][br]=b0.w;
            Bs[bk+4][br]=b1.x; Bs[bk+5][br]=b1.y; Bs[bk+6][br]=b1.z; Bs[bk+7][br]=b1.w;
        } else {
            int bk = tid >> 4;
            int bc = (tid & 15) * 8;
            float4 b0 = make_float4(0,0,0,0), b1 = b0;
            if (bn + bc < N){
                const float* bp = B + (size_t)(k0 + bk) * ldb + bn + bc;
                b0 = ld4(bp); b1 = ld4(bp + 4);
            }
            Bs[bk][bc+0]=b0.x; Bs[bk][bc+1]=b0.y; Bs[bk][bc+2]=b0.z; Bs[bk][bc+3]=b0.w;
            Bs[bk][bc+4]=b1.x; Bs[bk][bc+5]=b1.y; Bs[bk][bc+6]=b1.z; Bs[bk][bc+7]=b1.w;
        }
        __syncthreads();
        #pragma unroll
        for (int kk = 0; kk < BKK; kk++){
            float a[8], b[8];
            #pragma unroll
            for (int i = 0; i < 8; i++) a[i] = As[kk][ty*8 + i];
            #pragma unroll
            for (int j = 0; j < 8; j++) b[j] = Bs[kk][tx*8 + j];
            #pragma unroll
            for (int i = 0; i < 8; i++)
                #pragma unroll
                for (int j = 0; j < 8; j++)
                    acc[i][j] = fmaf(a[i], b[j], acc[i][j]);
        }
        __syncthreads();
    }
    #pragma unroll
    for (int i = 0; i < 8; i++){
        int row = bm + ty*8 + i;
        if (row < M){
            #pragma unroll
            for (int j = 0; j < 8; j += 4){
                int col = bn + tx*8 + j;
                st4(C + (size_t)row*ldc + col,
                    make_float4(acc[i][j], acc[i][j+1], acc[i][j+2], acc[i][j+3]));
            }
        }
    }
}

// ---------------- fused edge kernel: attention scalar + scatter, warp/edge ----------------
template<int D>
__global__ void k_edge(const int* __restrict__ el, const int* __restrict__ eln,
                       const int* __restrict__ et, const int* __restrict__ etn,
                       const float* __restrict__ sd, const float* __restrict__ ss,
                       const float* __restrict__ sr,
                       const float* __restrict__ Ps, const float* __restrict__ R,
                       float* __restrict__ rowsum, float* __restrict__ S)
{
    int e = (blockIdx.x * blockDim.x + threadIdx.x) >> 5;
    int lane = threadIdx.x & 31;
    if (e >= ET) return;
    int dst, src, r0, r1 = -1;
    bool onehop = (e < E1);
    if (onehop){
        dst = el[e]; src = el[E1 + e]; r0 = et[e];
    } else {
        int i = e - E1;
        dst = eln[i]; src = eln[EN + i];
        r0 = etn[2*i]; r1 = etn[2*i + 1];
    }
    float ee;
    if (lane == 0){
        float srv = onehop ? sr[r0] : (sr[r0] + sr[r1]);
        float s = sd[dst] + ss[src] + srv;
        float lk = s > 0.f ? s : 0.2f * s;
        ee = expf(-lk);
        atomicAdd(rowsum + dst, ee);
    }
    ee = __shfl_sync(0xffffffffu, ee, 0);
    #pragma unroll
    for (int c0 = 0; c0 < D; c0 += 128){
        int c = c0 + lane * 4;
        float4 p = ld4(Ps + (size_t)src * D + c);
        float4 r = ld4(R + (size_t)r0 * D + c);
        if (!onehop){
            float4 rb = ld4(R + (size_t)r1 * D + c);
            r.x += rb.x; r.y += rb.y; r.z += rb.z; r.w += rb.w;
        }
        float4 v = make_float4(ee*(p.x+r.x), ee*(p.y+r.y), ee*(p.z+r.z), ee*(p.w+r.w));
        red4(S + (size_t)dst * D + c, v);
    }
}

// ---------------- layer-1 finalize: x[n, h*128+c] = elu((rs*Pd + S)/rs_clamped) ----------------
__global__ void k_fin1(const float* __restrict__ Pd, const float* __restrict__ S,
                       const float* __restrict__ rs, float* __restrict__ x)
{
    int n = (blockIdx.x * blockDim.x + threadIdx.x) >> 5;
    int lane = threadIdx.x & 31;
    if (n >= NN) return;
    int c = lane * 4;
    #pragma unroll
    for (int h = 0; h < 2; h++){
        const float* Pdh = Pd + (size_t)h * NN * 128;
        const float* Sh  = S  + (size_t)h * NN * 128;
        float r  = rs[h*NN + n];
        float rc = (r == 0.f) ? 1e-12f : r;
        float4 pd = ld4(Pdh + (size_t)n*128 + c);
        float4 s  = ld4(Sh  + (size_t)n*128 + c);
        float4 hv;
        hv.x = elu1(fmaf(r, pd.x, s.x) / rc);
        hv.y = elu1(fmaf(r, pd.y, s.y) / rc);
        hv.z = elu1(fmaf(r, pd.z, s.z) / rc);
        hv.w = elu1(fmaf(r, pd.w, s.w) / rc);
        st4(x + (size_t)n*256 + h*128 + c, hv);
    }
}

// ---------------- mask ----------------
__global__ void k_setmask(const int* __restrict__ bi, float* __restrict__ mask){
    int i = blockIdx.x * blockDim.x + threadIdx.x;
    if (i < 4096) mask[bi[3*i + 2]] = 1.f;
}

// ---------------- final outputs: out_entity_1 and out_entity_l_1 ----------------
__global__ void k_final(const float* __restrict__ eup, const float* __restrict__ Xd,
                        const float* __restrict__ S2, const float* __restrict__ rs2,
                        const float* __restrict__ mask,
                        float* __restrict__ out1, float* __restrict__ out3)
{
    int n = (blockIdx.x * blockDim.x + threadIdx.x) >> 5;
    int lane = threadIdx.x & 31;
    if (n >= NN) return;
    float r  = rs2[n];
    float rc = (r == 0.f) ? 1e-12f : r;
    float mk = mask[n];
    float4 v1[2], v3[2];
    float ss1 = 0.f, ss3 = 0.f;
    #pragma unroll
    for (int q = 0; q < 2; q++){
        int c = q*128 + lane*4;
        float4 xd = ld4(Xd  + (size_t)n*256 + c);
        float4 s2 = ld4(S2  + (size_t)n*256 + c);
        float4 e4 = ld4(eup + (size_t)n*256 + c);
        float hr0 = fmaf(r, xd.x, s2.x);
        float hr1 = fmaf(r, xd.y, s2.y);
        float hr2 = fmaf(r, xd.z, s2.z);
        float hr3 = fmaf(r, xd.w, s2.w);
        float a0 = e4.x + mk * elu1(hr0 / rc);
        float a1 = e4.y + mk * elu1(hr1 / rc);
        float a2 = e4.z + mk * elu1(hr2 / rc);
        float a3 = e4.w + mk * elu1(hr3 / rc);
        float b0 = elu1(hr0), b1 = elu1(hr1), b2 = elu1(hr2), b3 = elu1(hr3);
        v1[q] = make_float4(a0, a1, a2, a3);
        v3[q] = make_float4(b0, b1, b2, b3);
        ss1 += a0*a0 + a1*a1 + a2*a2 + a3*a3;
        ss3 += b0*b0 + b1*b1 + b2*b2 + b3*b3;
    }
    ss1 = wred(ss1);
    ss3 = wred(ss3);
    float sc1 = 1.f / fmaxf(sqrtf(ss1), 1e-12f);
    float sc3 = 1.f / fmaxf(sqrtf(ss3), 1e-12f);
    #pragma unroll
    for (int q = 0; q < 2; q++){
        int c = q*128 + lane*4;
        st4(out1 + (size_t)n*256 + c, make_float4(v1[q].x*sc1, v1[q].y*sc1, v1[q].z*sc1, v1[q].w*sc1));
        st4(out3 + (size_t)n*256 + c, make_float4(v3[q].x*sc3, v3[q].y*sc3, v3[q].z*sc3, v3[q].w*sc3));
    }
}

// ---------------- host launch ----------------
static float* sym(const void* s){
    void* p = nullptr;
    cudaGetSymbolAddress(&p, s);
    return (float*)p;
}

extern "C" void kernel_launch(void* const* d_in, const int* in_sizes, int n_in,
                              void* d_out, int out_size)
{
    const float* ent    = (const float*)d_in[0];
    const float* rel    = (const float*)d_in[1];
    const float* a1     = (const float*)d_in[2];   // [2,128,384]
    const float* a2_1   = (const float*)d_in[3];   // [2,128]
    const float* W      = (const float*)d_in[4];   // [128,256]
    const float* a_out  = (const float*)d_in[5];   // [256,768]
    const float* a2_out = (const float*)d_in[6];   // [256]
    const float* W_ent  = (const float*)d_in[7];   // [128,256]
    const int*   bi     = (const int*)d_in[8];     // [4096,3]
    const int*   el     = (const int*)d_in[9];     // [2,300000]
    const int*   et     = (const int*)d_in[10];    // [300000]
    const int*   eln    = (const int*)d_in[11];    // [2,30000]
    const int*   etn    = (const int*)d_in[12];    // [30000,2]
    float* out = (float*)d_out;

    float* p_ent = sym(g_ent);
    float* p_Pd1 = sym(g_Pd1); float* p_Ps1 = sym(g_Ps1); float* p_R1 = sym(g_R1);
    float* p_sd1 = sym(g_sd1); float* p_ss1 = sym(g_ss1); float* p_sr1 = sym(g_sr1);
    float* p_rs1 = sym(g_rs1); float* p_S1  = sym(g_S1);  float* p_x  = sym(g_x);
    float* p_Xd  = sym(g_Xd);  float* p_Xs  = sym(g_Xs);  float* p_R2 = sym(g_R2);
    float* p_sd2 = sym(g_sd2); float* p_ss2 = sym(g_ss2); float* p_sr2 = sym(g_sr2);
    float* p_rs2 = sym(g_rs2); float* p_S2  = sym(g_S2);  float* p_eup = sym(g_eup);
    float* p_mask = sym(g_mask);

    const int T = 256;
    // zero accumulators + mask
    k_zero<<<2048, T>>>(p_S1,  2*NN*128);
    k_zero<<<2048, T>>>(p_S2,  NN*256);
    k_zero<<<256,  T>>>(p_rs1, 2*NN);
    k_zero<<<256,  T>>>(p_rs2, NN);
    k_zero<<<256,  T>>>(p_mask, NN);

    // l2 normalize entities
    k_l2norm128<<<(NN*32 + T-1)/T, T>>>(ent, p_ent);

    // layer-1 projections (2 heads)
    for (int h = 0; h < 2; h++){
        const float* ah = a1 + (size_t)h * 128 * 384;
        sgemm<true><<<dim3(1, (NN+127)/128), T>>>(p_ent, 128, ah,       384, p_Pd1 + (size_t)h*NN*128, 128, NN,   128, 128);
        sgemm<true><<<dim3(1, (NN+127)/128), T>>>(p_ent, 128, ah + 128, 384, p_Ps1 + (size_t)h*NN*128, 128, NN,   128, 128);
        sgemm<true><<<dim3(1, 2),            T>>>(rel,   128, ah + 256, 384, p_R1  + (size_t)h*NREL*128,128, NREL, 128, 128);
        k_rowdot<<<(NN*32 + T-1)/T, T>>>(p_Pd1 + (size_t)h*NN*128, a2_1 + h*128, p_sd1 + h*NN, NN, 128);
        k_rowdot<<<(NN*32 + T-1)/T, T>>>(p_Ps1 + (size_t)h*NN*128, a2_1 + h*128, p_ss1 + h*NN, NN, 128);
        k_rowdot<<<(NREL*32 + T-1)/T, T>>>(p_R1 + (size_t)h*NREL*128, a2_1 + h*128, p_sr1 + h*NREL, NREL, 128);
        k_edge<128><<<(ET*32 + T-1)/T, T>>>(el, eln, et, etn,
            p_sd1 + h*NN, p_ss1 + h*NN, p_sr1 + h*NREL,
            p_Ps1 + (size_t)h*NN*128, p_R1 + (size_t)h*NREL*128,
            p_rs1 + h*NN, p_S1 + (size_t)h*NN*128);
    }
    k_fin1<<<(NN*32 + T-1)/T, T>>>(p_Pd1, p_S1, p_rs1, p_x);

    // out_relation_1 = rel @ W  -> directly into output
    sgemm<false><<<dim3(2, 2), T>>>(rel, 128, W, 256, out + OREL, 256, NREL, 256, 128);

    // layer-2 projections
    sgemm<true><<<dim3(2, (NN+127)/128), T>>>(p_x, 256, a_out,       768, p_Xd, 256, NN,   256, 256);
    sgemm<true><<<dim3(2, (NN+127)/128), T>>>(p_x, 256, a_out + 256, 768, p_Xs, 256, NN,   256, 256);
    sgemm<true><<<dim3(2, 2),            T>>>(out + OREL, 256, a_out + 512, 768, p_R2, 256, NREL, 256, 256);

    // entities_upgraded = ent_n @ W_entities
    sgemm<false><<<dim3(2, (NN+127)/128), T>>>(p_ent, 128, W_ent, 256, p_eup, 256, NN, 256, 128);

    k_rowdot<<<(NN*32 + T-1)/T, T>>>(p_Xd, a2_out, p_sd2, NN, 256);
    k_rowdot<<<(NN*32 + T-1)/T, T>>>(p_Xs, a2_out, p_ss2, NN, 256);
    k_rowdot<<<(NREL*32 + T-1)/T, T>>>(p_R2, a2_out, p_sr2, NREL, 256);

    k_edge<256><<<(ET*32 + T-1)/T, T>>>(el, eln, et, etn,
        p_sd2, p_ss2, p_sr2, p_Xs, p_R2, p_rs2, p_S2);

    k_setmask<<<16, T>>>(bi, p_mask);

    k_final<<<(NN*32 + T-1)/T, T>>>(p_eup, p_Xd, p_S2, p_rs2, p_mask,
                                    out /*out_entity_1*/, out + O3 /*out_entity_l_1*/);
}

// round 2
// speedup vs baseline: 1.5979x; 1.5979x over previous
#include <cuda_runtime.h>
#include <math.h>

#define NN   50000
#define E1   300000
#define EN   30000
#define ET   330000
#define OREL 12800000      // 50000*256
#define O3   12865536      // + 256*256
#define NREL 256

// ---------------- device scratch (static, allocation-free) ----------------
__device__ float g_ent[NN*128];
__device__ float g_Pd1[2*NN*128];
__device__ float g_Ps1[2*NN*128];
__device__ float g_R1 [2*NREL*128];
__device__ float g_sd1[2*NN];
__device__ float g_ss1[2*NN];
__device__ float g_sr1[2*NREL];
__device__ float g_rs1[2*NN];
__device__ float g_S1 [2*NN*128];
__device__ float g_x  [NN*256];
__device__ float g_Xd [NN*256];
__device__ float g_Xs [NN*256];
__device__ float g_R2 [NREL*256];
__device__ float g_sd2[NN];
__device__ float g_ss2[NN];
__device__ float g_sr2[NREL];
__device__ float g_rs2[NN];
__device__ float g_S2 [NN*256];
__device__ float g_eup[NN*256];
__device__ float g_mask[NN];
__device__ float g_Wt [256*128];
__device__ float g_Wet[256*128];

// ---------------- helpers ----------------
__device__ __forceinline__ float4 ld4(const float* p){ return *reinterpret_cast<const float4*>(p); }
__device__ __forceinline__ void   st4(float* p, float4 v){ *reinterpret_cast<float4*>(p) = v; }
__device__ __forceinline__ float  elu1(float x){ return x > 0.f ? x : expm1f(x); }
__device__ __forceinline__ float  wred(float v){
    #pragma unroll
    for (int o = 16; o; o >>= 1) v += __shfl_xor_sync(0xffffffffu, v, o);
    return v;
}
__device__ __forceinline__ void red4(float* p, float4 v){
    asm volatile("red.global.add.v4.f32 [%0], {%1, %2, %3, %4};"
                 :: "l"(p), "f"(v.x), "f"(v.y), "f"(v.z), "f"(v.w) : "memory");
}
__device__ __forceinline__ float f2tf32(float x){
    unsigned u;
    asm("cvt.rna.tf32.f32 %0, %1;" : "=r"(u) : "f"(x));
    return __uint_as_float(u);
}
__device__ __forceinline__ void mma_tf32(float* c, const float* a, const float* b){
    asm volatile("mma.sync.aligned.m16n8k8.row.col.f32.tf32.tf32.f32 "
        "{%0,%1,%2,%3}, {%4,%5,%6,%7}, {%8,%9}, {%0,%1,%2,%3};"
        : "+f"(c[0]), "+f"(c[1]), "+f"(c[2]), "+f"(c[3])
        : "r"(__float_as_uint(a[0])), "r"(__float_as_uint(a[1])),
          "r"(__float_as_uint(a[2])), "r"(__float_as_uint(a[3])),
          "r"(__float_as_uint(b[0])), "r"(__float_as_uint(b[1])));
}

// ---------------- zero fill ----------------
__global__ void k_zero(float* __restrict__ p, int n){
    int i  = blockIdx.x * blockDim.x + threadIdx.x;
    int st = gridDim.x * blockDim.x;
    for (; i < n; i += st) p[i] = 0.f;
}

// ---------------- transpose: in[R][C] -> out[C][R] ----------------
__global__ void k_transpose(const float* __restrict__ in, float* __restrict__ out, int R, int C){
    int i = blockIdx.x * blockDim.x + threadIdx.x;
    if (i < R*C){ int r = i / C, c = i % C; out[c*R + r] = in[i]; }
}

// ---------------- row l2-normalize, D=128, warp/row ----------------
__global__ void k_l2norm128(const float* __restrict__ in, float* __restrict__ out){
    int n = (blockIdx.x * blockDim.x + threadIdx.x) >> 5;
    int lane = threadIdx.x & 31;
    if (n >= NN) return;
    int c = lane * 4;
    float4 v = ld4(in + (size_t)n*128 + c);
    float ss = v.x*v.x + v.y*v.y + v.z*v.z + v.w*v.w;
    ss = wred(ss);
    float s = 1.f / fmaxf(sqrtf(ss), 1e-12f);
    st4(out + (size_t)n*128 + c, make_float4(v.x*s, v.y*s, v.z*s, v.w*s));
}

// ---------------- row dot with vector, warp/row ----------------
__global__ void k_rowdot(const float* __restrict__ A, const float* __restrict__ v,
                         float* __restrict__ out, int M, int D){
    int r = (blockIdx.x * blockDim.x + threadIdx.x) >> 5;
    int lane = threadIdx.x & 31;
    if (r >= M) return;
    float acc = 0.f;
    for (int c = lane * 4; c < D; c += 128){
        float4 a = ld4(A + (size_t)r*D + c);
        float4 b = ld4(v + c);
        acc += a.x*b.x + a.y*b.y + a.z*b.z + a.w*b.w;
    }
    acc = wred(acc);
    if (lane == 0) out[r] = acc;
}

// ---------------- TF32 tensor-core GEMM (TN): C[M,N] = A[M,K] * B[N,K]^T ----------------
// A row-major (lda = row stride), B row-major [N,K] (ldb = row stride), C row-major.
// Requires: K % 16 == 0, N covered exactly by grid.x*128.
__global__ __launch_bounds__(256, 2)
void gemm_tn_tf32(const float* __restrict__ A, int lda,
                  const float* __restrict__ B, int ldb,
                  float* __restrict__ C, int ldc,
                  int M, int N, int K)
{
    __shared__ float As[16][136];
    __shared__ float Bs[16][136];
    const int bm = blockIdx.y * 128;
    const int bn = blockIdx.x * 128;
    const int tid  = threadIdx.x;
    const int warp = tid >> 5;
    const int lane = tid & 31;
    const int wm = (warp & 1) * 64;
    const int wn = (warp >> 1) * 32;
    const int g = lane >> 2;
    const int t = lane & 3;

    float acc[4][4][4];
    #pragma unroll
    for (int i = 0; i < 4; i++)
        #pragma unroll
        for (int j = 0; j < 4; j++)
            #pragma unroll
            for (int q = 0; q < 4; q++) acc[i][j][q] = 0.f;

    const int ar = tid >> 1;          // 0..127
    const int ak = (tid & 1) * 8;     // 0 or 8
    const bool avalid = (bm + ar) < M;
    const bool bvalid = (bn + ar) < N;
    const float* Ap = A + (size_t)(bm + ar) * lda + ak;
    const float* Bp = B + (size_t)(bn + ar) * ldb + ak;

    for (int k0 = 0; k0 < K; k0 += 16){
        float4 a0 = make_float4(0,0,0,0), a1 = a0, b0 = a0, b1 = a0;
        if (avalid){ a0 = ld4(Ap + k0); a1 = ld4(Ap + k0 + 4); }
        if (bvalid){ b0 = ld4(Bp + k0); b1 = ld4(Bp + k0 + 4); }
        As[ak+0][ar] = f2tf32(a0.x); As[ak+1][ar] = f2tf32(a0.y);
        As[ak+2][ar] = f2tf32(a0.z); As[ak+3][ar] = f2tf32(a0.w);
        As[ak+4][ar] = f2tf32(a1.x); As[ak+5][ar] = f2tf32(a1.y);
        As[ak+6][ar] = f2tf32(a1.z); As[ak+7][ar] = f2tf32(a1.w);
        Bs[ak+0][ar] = f2tf32(b0.x); Bs[ak+1][ar] = f2tf32(b0.y);
        Bs[ak+2][ar] = f2tf32(b0.z); Bs[ak+3][ar] = f2tf32(b0.w);
        Bs[ak+4][ar] = f2tf32(b1.x); Bs[ak+5][ar] = f2tf32(b1.y);
        Bs[ak+6][ar] = f2tf32(b1.z); Bs[ak+7][ar] = f2tf32(b1.w);
        __syncthreads();

        #pragma unroll
        for (int ks = 0; ks < 16; ks += 8){
            float aR[4][4];
            float bR[4][2];
            #pragma unroll
            for (int mi = 0; mi < 4; mi++){
                int m0 = wm + mi*16 + g;
                aR[mi][0] = As[ks + t    ][m0    ];
                aR[mi][1] = As[ks + t    ][m0 + 8];
                aR[mi][2] = As[ks + t + 4][m0    ];
                aR[mi][3] = As[ks + t + 4][m0 + 8];
            }
            #pragma unroll
            for (int ni = 0; ni < 4; ni++){
                int n0 = wn + ni*8 + g;
                bR[ni][0] = Bs[ks + t    ][n0];
                bR[ni][1] = Bs[ks + t + 4][n0];
            }
            #pragma unroll
            for (int mi = 0; mi < 4; mi++)
                #pragma unroll
                for (int ni = 0; ni < 4; ni++)
                    mma_tf32(acc[mi][ni], aR[mi], bR[ni]);
        }
        __syncthreads();
    }

    // epilogue: c0=C[g][2t], c1=C[g][2t+1], c2=C[g+8][2t], c3=C[g+8][2t+1]
    #pragma unroll
    for (int mi = 0; mi < 4; mi++){
        int r0 = bm + wm + mi*16 + g;
        #pragma unroll
        for (int ni = 0; ni < 4; ni++){
            int c0 = bn + wn + ni*8 + 2*t;
            if (r0 < M)
                *reinterpret_cast<float2*>(C + (size_t)r0*ldc + c0)
                    = make_float2(acc[mi][ni][0], acc[mi][ni][1]);
            if (r0 + 8 < M)
                *reinterpret_cast<float2*>(C + (size_t)(r0+8)*ldc + c0)
                    = make_float2(acc[mi][ni][2], acc[mi][ni][3]);
        }
    }
}

// ---------------- fused edge kernel: attention scalar + scatter, warp/edge ----------------
template<int D>
__global__ void k_edge(const int* __restrict__ el, const int* __restrict__ eln,
                       const int* __restrict__ et, const int* __restrict__ etn,
                       const float* __restrict__ sd, const float* __restrict__ ss,
                       const float* __restrict__ sr,
                       const float* __restrict__ Ps, const float* __restrict__ R,
                       float* __restrict__ rowsum, float* __restrict__ S)
{
    int e = (blockIdx.x * blockDim.x + threadIdx.x) >> 5;
    int lane = threadIdx.x & 31;
    if (e >= ET) return;
    int dst, src, r0, r1 = -1;
    bool onehop = (e < E1);
    if (onehop){
        dst = el[e]; src = el[E1 + e]; r0 = et[e];
    } else {
        int i = e - E1;
        dst = eln[i]; src = eln[EN + i];
        r0 = etn[2*i]; r1 = etn[2*i + 1];
    }
    float ee;
    if (lane == 0){
        float srv = onehop ? sr[r0] : (sr[r0] + sr[r1]);
        float s = sd[dst] + ss[src] + srv;
        float lk = s > 0.f ? s : 0.2f * s;
        ee = expf(-lk);
        atomicAdd(rowsum + dst, ee);
    }
    ee = __shfl_sync(0xffffffffu, ee, 0);
    #pragma unroll
    for (int c0 = 0; c0 < D; c0 += 128){
        int c = c0 + lane * 4;
        float4 p = ld4(Ps + (size_t)src * D + c);
        float4 r = ld4(R + (size_t)r0 * D + c);
        if (!onehop){
            float4 rb = ld4(R + (size_t)r1 * D + c);
            r.x += rb.x; r.y += rb.y; r.z += rb.z; r.w += rb.w;
        }
        float4 v = make_float4(ee*(p.x+r.x), ee*(p.y+r.y), ee*(p.z+r.z), ee*(p.w+r.w));
        red4(S + (size_t)dst * D + c, v);
    }
}

// ---------------- layer-1 finalize ----------------
__global__ void k_fin1(const float* __restrict__ Pd, const float* __restrict__ S,
                       const float* __restrict__ rs, float* __restrict__ x)
{
    int n = (blockIdx.x * blockDim.x + threadIdx.x) >> 5;
    int lane = threadIdx.x & 31;
    if (n >= NN) return;
    int c = lane * 4;
    #pragma unroll
    for (int h = 0; h < 2; h++){
        const float* Pdh = Pd + (size_t)h * NN * 128;
        const float* Sh  = S  + (size_t)h * NN * 128;
        float r  = rs[h*NN + n];
        float rc = (r == 0.f) ? 1e-12f : r;
        float4 pd = ld4(Pdh + (size_t)n*128 + c);
        float4 s  = ld4(Sh  + (size_t)n*128 + c);
        float4 hv;
        hv.x = elu1(fmaf(r, pd.x, s.x) / rc);
        hv.y = elu1(fmaf(r, pd.y, s.y) / rc);
        hv.z = elu1(fmaf(r, pd.z, s.z) / rc);
        hv.w = elu1(fmaf(r, pd.w, s.w) / rc);
        st4(x + (size_t)n*256 + h*128 + c, hv);
    }
}

// ---------------- mask ----------------
__global__ void k_setmask(const int* __restrict__ bi, float* __restrict__ mask){
    int i = blockIdx.x * blockDim.x + threadIdx.x;
    if (i < 4096) mask[bi[3*i + 2]] = 1.f;
}

// ---------------- final outputs ----------------
__global__ void k_final(const float* __restrict__ eup, const float* __restrict__ Xd,
                        const float* __restrict__ S2, const float* __restrict__ rs2,
                        const float* __restrict__ mask,
                        float* __restrict__ out1, float* __restrict__ out3)
{
    int n = (blockIdx.x * blockDim.x + threadIdx.x) >> 5;
    int lane = threadIdx.x & 31;
    if (n >= NN) return;
    float r  = rs2[n];
    float rc = (r == 0.f) ? 1e-12f : r;
    float mk = mask[n];
    float4 v1[2], v3[2];
    float ss1 = 0.f, ss3 = 0.f;
    #pragma unroll
    for (int q = 0; q < 2; q++){
        int c = q*128 + lane*4;
        float4 xd = ld4(Xd  + (size_t)n*256 + c);
        float4 s2 = ld4(S2  + (size_t)n*256 + c);
        float4 e4 = ld4(eup + (size_t)n*256 + c);
        float hr0 = fmaf(r, xd.x, s2.x);
        float hr1 = fmaf(r, xd.y, s2.y);
        float hr2 = fmaf(r, xd.z, s2.z);
        float hr3 = fmaf(r, xd.w, s2.w);
        float a0 = e4.x + mk * elu1(hr0 / rc);
        float a1 = e4.y + mk * elu1(hr1 / rc);
        float a2 = e4.z + mk * elu1(hr2 / rc);
        float a3 = e4.w + mk * elu1(hr3 / rc);
        float b0 = elu1(hr0), b1 = elu1(hr1), b2 = elu1(hr2), b3 = elu1(hr3);
        v1[q] = make_float4(a0, a1, a2, a3);
        v3[q] = make_float4(b0, b1, b2, b3);
        ss1 += a0*a0 + a1*a1 + a2*a2 + a3*a3;
        ss3 += b0*b0 + b1*b1 + b2*b2 + b3*b3;
    }
    ss1 = wred(ss1);
    ss3 = wred(ss3);
    float sc1 = 1.f / fmaxf(sqrtf(ss1), 1e-12f);
    float sc3 = 1.f / fmaxf(sqrtf(ss3), 1e-12f);
    #pragma unroll
    for (int q = 0; q < 2; q++){
        int c = q*128 + lane*4;
        st4(out1 + (size_t)n*256 + c, make_float4(v1[q].x*sc1, v1[q].y*sc1, v1[q].z*sc1, v1[q].w*sc1));
        st4(out3 + (size_t)n*256 + c, make_float4(v3[q].x*sc3, v3[q].y*sc3, v3[q].z*sc3, v3[q].w*sc3));
    }
}

// ---------------- host launch ----------------
static float* sym(const void* s){
    void* p = nullptr;
    cudaGetSymbolAddress(&p, s);
    return (float*)p;
}

extern "C" void kernel_launch(void* const* d_in, const int* in_sizes, int n_in,
                              void* d_out, int out_size)
{
    const float* ent    = (const float*)d_in[0];
    const float* rel    = (const float*)d_in[1];
    const float* a1     = (const float*)d_in[2];   // [2,128,384]
    const float* a2_1   = (const float*)d_in[3];   // [2,128]
    const float* W      = (const float*)d_in[4];   // [128,256]
    const float* a_out  = (const float*)d_in[5];   // [256,768]
    const float* a2_out = (const float*)d_in[6];   // [256]
    const float* W_ent  = (const float*)d_in[7];   // [128,256]
    const int*   bi     = (const int*)d_in[8];     // [4096,3]
    const int*   el     = (const int*)d_in[9];     // [2,300000]
    const int*   et     = (const int*)d_in[10];    // [300000]
    const int*   eln    = (const int*)d_in[11];    // [2,30000]
    const int*   etn    = (const int*)d_in[12];    // [30000,2]
    float* out = (float*)d_out;

    float* p_ent = sym(g_ent);
    float* p_Pd1 = sym(g_Pd1); float* p_Ps1 = sym(g_Ps1); float* p_R1 = sym(g_R1);
    float* p_sd1 = sym(g_sd1); float* p_ss1 = sym(g_ss1); float* p_sr1 = sym(g_sr1);
    float* p_rs1 = sym(g_rs1); float* p_S1  = sym(g_S1);  float* p_x  = sym(g_x);
    float* p_Xd  = sym(g_Xd);  float* p_Xs  = sym(g_Xs);  float* p_R2 = sym(g_R2);
    float* p_sd2 = sym(g_sd2); float* p_ss2 = sym(g_ss2); float* p_sr2 = sym(g_sr2);
    float* p_rs2 = sym(g_rs2); float* p_S2  = sym(g_S2);  float* p_eup = sym(g_eup);
    float* p_mask = sym(g_mask);
    float* p_Wt  = sym(g_Wt);  float* p_Wet = sym(g_Wet);

    const int T = 256;
    const int GY = (NN + 127) / 128;   // 391

    // zero accumulators + mask
    k_zero<<<2048, T>>>(p_S1,  2*NN*128);
    k_zero<<<2048, T>>>(p_S2,  NN*256);
    k_zero<<<256,  T>>>(p_rs1, 2*NN);
    k_zero<<<256,  T>>>(p_rs2, NN);
    k_zero<<<256,  T>>>(p_mask, NN);

    // weight transposes for TN GEMM
    k_transpose<<<(128*256 + T-1)/T, T>>>(W,     p_Wt,  128, 256);
    k_transpose<<<(128*256 + T-1)/T, T>>>(W_ent, p_Wet, 128, 256);

    // l2 normalize entities
    k_l2norm128<<<(NN*32 + T-1)/T, T>>>(ent, p_ent);

    // layer-1 projections (2 heads)
    for (int h = 0; h < 2; h++){
        const float* ah = a1 + (size_t)h * 128 * 384;
        gemm_tn_tf32<<<dim3(1, GY), T>>>(p_ent, 128, ah,       384, p_Pd1 + (size_t)h*NN*128,   128, NN,   128, 128);
        gemm_tn_tf32<<<dim3(1, GY), T>>>(p_ent, 128, ah + 128, 384, p_Ps1 + (size_t)h*NN*128,   128, NN,   128, 128);
        gemm_tn_tf32<<<dim3(1, 2),  T>>>(rel,   128, ah + 256, 384, p_R1  + (size_t)h*NREL*128, 128, NREL, 128, 128);
        k_rowdot<<<(NN*32 + T-1)/T, T>>>(p_Pd1 + (size_t)h*NN*128, a2_1 + h*128, p_sd1 + h*NN, NN, 128);
        k_rowdot<<<(NN*32 + T-1)/T, T>>>(p_Ps1 + (size_t)h*NN*128, a2_1 + h*128, p_ss1 + h*NN, NN, 128);
        k_rowdot<<<(NREL*32 + T-1)/T, T>>>(p_R1 + (size_t)h*NREL*128, a2_1 + h*128, p_sr1 + h*NREL, NREL, 128);
        k_edge<128><<<(ET*32 + T-1)/T, T>>>(el, eln, et, etn,
            p_sd1 + h*NN, p_ss1 + h*NN, p_sr1 + h*NREL,
            p_Ps1 + (size_t)h*NN*128, p_R1 + (size_t)h*NREL*128,
            p_rs1 + h*NN, p_S1 + (size_t)h*NN*128);
    }
    k_fin1<<<(NN*32 + T-1)/T, T>>>(p_Pd1, p_S1, p_rs1, p_x);

    // out_relation_1 = rel @ W  -> directly into output
    gemm_tn_tf32<<<dim3(2, 2), T>>>(rel, 128, p_Wt, 128, out + OREL, 256, NREL, 256, 128);

    // layer-2 projections
    gemm_tn_tf32<<<dim3(2, GY), T>>>(p_x, 256, a_out,       768, p_Xd, 256, NN,   256, 256);
    gemm_tn_tf32<<<dim3(2, GY), T>>>(p_x, 256, a_out + 256, 768, p_Xs, 256, NN,   256, 256);
    gemm_tn_tf32<<<dim3(2, 2),  T>>>(out + OREL, 256, a_out + 512, 768, p_R2, 256, NREL, 256, 256);

    // entities_upgraded = ent_n @ W_entities
    gemm_tn_tf32<<<dim3(2, GY), T>>>(p_ent, 128, p_Wet, 128, p_eup, 256, NN, 256, 128);

    k_rowdot<<<(NN*32 + T-1)/T, T>>>(p_Xd, a2_out, p_sd2, NN, 256);
    k_rowdot<<<(NN*32 + T-1)/T, T>>>(p_Xs, a2_out, p_ss2, NN, 256);
    k_rowdot<<<(NREL*32 + T-1)/T, T>>>(p_R2, a2_out, p_sr2, NREL, 256);

    k_edge<256><<<(ET*32 + T-1)/T, T>>>(el, eln, et, etn,
        p_sd2, p_ss2, p_sr2, p_Xs, p_R2, p_rs2, p_S2);

    k_setmask<<<16, T>>>(bi, p_mask);

    k_final<<<(NN*32 + T-1)/T, T>>>(p_eup, p_Xd, p_S2, p_rs2, p_mask,
                                    out /*out_entity_1*/, out + O3 /*out_entity_l_1*/);
}

// round 3
// speedup vs baseline: 1.8526x; 1.1594x over previous
#include <cuda_runtime.h>
#include <math.h>

#define NN   50000
#define E1   300000
#define EN   30000
#define ET   330000
#define OREL 12800000      // 50000*256
#define O3   12865536      // + 256*256
#define NREL 256

// ---------------- device scratch (static, allocation-free) ----------------
// zeroed-every-call region
#define OFF_S1   0                       // [NN*256]  layer-1 scatter (h0|h1)
#define OFF_S2   (NN*256)                // [NN*256]  layer-2 scatter
#define OFF_RS1  (2*NN*256)              // [2*NN]
#define OFF_RS2  (2*NN*256 + 2*NN)       // [NN]
#define OFF_MASK (2*NN*256 + 3*NN)       // [NN]
#define ZN       (2*NN*256 + 4*NN)
__device__ float g_Z[ZN];

__device__ float g_ent[NN*128];
__device__ float g_Pd [NN*512];     // cols 0:128 Pd_h0 | 128:256 Pd_h1 | 256:512 eup
__device__ float g_Ps [NN*256];     // cols 0:128 Ps_h0 | 128:256 Ps_h1   (gathered)
__device__ float g_R1 [NREL*256];   // cols 0:128 R_h0  | 128:256 R_h1
__device__ float g_x  [NN*256];
__device__ float g_Xd [NN*256];
__device__ float g_Xs [NN*256];     // gathered
__device__ float g_R2 [NREL*256];
__device__ float g_sd1[2*NN];
__device__ float g_ss1[2*NN];
__device__ float g_sr1[2*NREL];
__device__ float g_sd2[NN];
__device__ float g_ss2[NN];
__device__ float g_sr2[NREL];
// packed B matrices ([N][K] row-major for TN gemm)
__device__ float g_B1d[512*128];    // (a_d h0 | a_d h1 | W_ent^T)
__device__ float g_B1s[256*128];    // (a_s h0 | a_s h1)
__device__ float g_BR1[256*128];    // (a_r h0 | a_r h1)
__device__ float g_B2d[256*256];    // a_out[:, 0:256]
__device__ float g_B2s[256*256];    // a_out[:, 256:512]
__device__ float g_B3 [256*256];    // a_out[:, 512:768]
__device__ float g_BW [256*128];    // W^T

// ---------------- helpers ----------------
__device__ __forceinline__ float4 ld4(const float* p){ return *reinterpret_cast<const float4*>(p); }
__device__ __forceinline__ void   st4(float* p, float4 v){ *reinterpret_cast<float4*>(p) = v; }
__device__ __forceinline__ float  elu1(float x){ return x > 0.f ? x : expm1f(x); }
__device__ __forceinline__ float  wred(float v){
    #pragma unroll
    for (int o = 16; o; o >>= 1) v += __shfl_xor_sync(0xffffffffu, v, o);
    return v;
}
__device__ __forceinline__ void red4(float* p, float4 v){
    asm volatile("red.global.add.v4.f32 [%0], {%1, %2, %3, %4};"
                 :: "l"(p), "f"(v.x), "f"(v.y), "f"(v.z), "f"(v.w) : "memory");
}
__device__ __forceinline__ float f2tf32(float x){
    unsigned u;
    asm("cvt.rna.tf32.f32 %0, %1;" : "=r"(u) : "f"(x));
    return __uint_as_float(u);
}
__device__ __forceinline__ void mma_tf32(float* c, const float* a, const float* b){
    asm volatile("mma.sync.aligned.m16n8k8.row.col.f32.tf32.tf32.f32 "
        "{%0,%1,%2,%3}, {%4,%5,%6,%7}, {%8,%9}, {%0,%1,%2,%3};"
        : "+f"(c[0]), "+f"(c[1]), "+f"(c[2]), "+f"(c[3])
        : "r"(__float_as_uint(a[0])), "r"(__float_as_uint(a[1])),
          "r"(__float_as_uint(a[2])), "r"(__float_as_uint(a[3])),
          "r"(__float_as_uint(b[0])), "r"(__float_as_uint(b[1])));
}
__device__ __forceinline__ float dot4(float4 a, float4 b){
    return a.x*b.x + a.y*b.y + a.z*b.z + a.w*b.w;
}

// ---------------- zero fill (float4) ----------------
__global__ void k_zero4(float4* __restrict__ p, int n4){
    int i  = blockIdx.x * blockDim.x + threadIdx.x;
    int st = gridDim.x * blockDim.x;
    float4 z = make_float4(0,0,0,0);
    for (; i < n4; i += st) p[i] = z;
}

// ---------------- pack all B matrices ----------------
__global__ void k_packs(const float* __restrict__ a1, const float* __restrict__ a_out,
                        const float* __restrict__ W,  const float* __restrict__ W_ent,
                        float* __restrict__ B1d, float* __restrict__ B1s,
                        float* __restrict__ BR1, float* __restrict__ B2d,
                        float* __restrict__ B2s, float* __restrict__ B3,
                        float* __restrict__ BW)
{
    int i = blockIdx.x * blockDim.x + threadIdx.x;
    if (i < 512*128){                       // B1d
        int r = i >> 7, k = i & 127;
        float v;
        if (r < 256){ int h = r >> 7, rr = r & 127; v = a1[h*128*384 + rr*384 + k]; }
        else        { v = W_ent[k*256 + (r - 256)]; }
        B1d[i] = v; return;
    }
    i -= 512*128;
    if (i < 256*128){                       // B1s
        int r = i >> 7, k = i & 127;
        int h = r >> 7, rr = r & 127;
        B1s[i] = a1[h*128*384 + rr*384 + 128 + k]; return;
    }
    i -= 256*128;
    if (i < 256*128){                       // BR1
        int r = i >> 7, k = i & 127;
        int h = r >> 7, rr = r & 127;
        BR1[i] = a1[h*128*384 + rr*384 + 256 + k]; return;
    }
    i -= 256*128;
    if (i < 256*256){ int r = i >> 8, k = i & 255; B2d[i] = a_out[r*768 + k];       return; }
    i -= 256*256;
    if (i < 256*256){ int r = i >> 8, k = i & 255; B2s[i] = a_out[r*768 + 256 + k]; return; }
    i -= 256*256;
    if (i < 256*256){ int r = i >> 8, k = i & 255; B3[i]  = a_out[r*768 + 512 + k]; return; }
    i -= 256*256;
    if (i < 256*128){ int r = i >> 7, k = i & 127; BW[i]  = W[k*256 + r];           return; }
}

// ---------------- row l2-normalize, D=128, warp/row ----------------
__global__ void k_l2norm128(const float* __restrict__ in, float* __restrict__ out){
    int n = (blockIdx.x * blockDim.x + threadIdx.x) >> 5;
    int lane = threadIdx.x & 31;
    if (n >= NN) return;
    int c = lane * 4;
    float4 v = ld4(in + (size_t)n*128 + c);
    float ss = dot4(v, v);
    ss = wred(ss);
    float s = 1.f / fmaxf(sqrtf(ss), 1e-12f);
    st4(out + (size_t)n*128 + c, make_float4(v.x*s, v.y*s, v.z*s, v.w*s));
}

// ---------------- mask ----------------
__global__ void k_setmask(const int* __restrict__ bi, float* __restrict__ mask){
    int i = blockIdx.x * blockDim.x + threadIdx.x;
    if (i < 4096) mask[bi[3*i + 2]] = 1.f;
}

// ---------------- generic strided rowdot: out[r] = A[r*ld + ofs : +D] . v ----------------
__global__ void k_rowdot(const float* __restrict__ A, int ld, int D,
                         const float* __restrict__ v, float* __restrict__ out, int M){
    int r = (blockIdx.x * blockDim.x + threadIdx.x) >> 5;
    int lane = threadIdx.x & 31;
    if (r >= M) return;
    float acc = 0.f;
    for (int c = lane * 4; c < D; c += 128)
        acc += dot4(ld4(A + (size_t)r*ld + c), ld4(v + c));
    acc = wred(acc);
    if (lane == 0) out[r] = acc;
}

// ---------------- fused layer-1 attention-scalar dots ----------------
__global__ void k_dots1(const float* __restrict__ Pd, const float* __restrict__ Ps,
                        const float* __restrict__ a2, float* __restrict__ sd, float* __restrict__ ss){
    int n = (blockIdx.x * blockDim.x + threadIdx.x) >> 5;
    int lane = threadIdx.x & 31;
    if (n >= NN) return;
    int c = lane * 4;
    float4 b0 = ld4(a2 + c), b1 = ld4(a2 + 128 + c);
    float d0 = dot4(ld4(Pd + (size_t)n*512 + c),       b0);
    float d1 = dot4(ld4(Pd + (size_t)n*512 + 128 + c), b1);
    float s0 = dot4(ld4(Ps + (size_t)n*256 + c),       b0);
    float s1 = dot4(ld4(Ps + (size_t)n*256 + 128 + c), b1);
    d0 = wred(d0); d1 = wred(d1); s0 = wred(s0); s1 = wred(s1);
    if (lane == 0){ sd[n] = d0; sd[NN + n] = d1; ss[n] = s0; ss[NN + n] = s1; }
}

// ---------------- fused layer-2 attention-scalar dots ----------------
__global__ void k_dots2(const float* __restrict__ Xd, const float* __restrict__ Xs,
                        const float* __restrict__ a2, float* __restrict__ sd, float* __restrict__ ss){
    int n = (blockIdx.x * blockDim.x + threadIdx.x) >> 5;
    int lane = threadIdx.x & 31;
    if (n >= NN) return;
    float d = 0.f, s = 0.f;
    #pragma unroll
    for (int c0 = 0; c0 < 256; c0 += 128){
        int c = c0 + lane*4;
        float4 b = ld4(a2 + c);
        d += dot4(ld4(Xd + (size_t)n*256 + c), b);
        s += dot4(ld4(Xs + (size_t)n*256 + c), b);
    }
    d = wred(d); s = wred(s);
    if (lane == 0){ sd[n] = d; ss[n] = s; }
}

// ---------------- TF32 tensor-core GEMM (TN): C[M,N] = A[M,K] * B[N,K]^T ----------------
__global__ __launch_bounds__(256, 2)
void gemm_tn_tf32(const float* __restrict__ A, int lda,
                  const float* __restrict__ B, int ldb,
                  float* __restrict__ C, int ldc,
                  int M, int N, int K)
{
    __shared__ float As[16][136];
    __shared__ float Bs[16][136];
    const int bm = blockIdx.y * 128;
    const int bn = blockIdx.x * 128;
    const int tid  = threadIdx.x;
    const int warp = tid >> 5;
    const int lane = tid & 31;
    const int wm = (warp & 1) * 64;
    const int wn = (warp >> 1) * 32;
    const int g = lane >> 2;
    const int t = lane & 3;

    float acc[4][4][4];
    #pragma unroll
    for (int i = 0; i < 4; i++)
        #pragma unroll
        for (int j = 0; j < 4; j++)
            #pragma unroll
            for (int q = 0; q < 4; q++) acc[i][j][q] = 0.f;

    const int ar = tid >> 1;
    const int ak = (tid & 1) * 8;
    const bool avalid = (bm + ar) < M;
    const bool bvalid = (bn + ar) < N;
    const float* Ap = A + (size_t)(bm + ar) * lda + ak;
    const float* Bp = B + (size_t)(bn + ar) * ldb + ak;

    for (int k0 = 0; k0 < K; k0 += 16){
        float4 a0 = make_float4(0,0,0,0), a1 = a0, b0 = a0, b1 = a0;
        if (avalid){ a0 = ld4(Ap + k0); a1 = ld4(Ap + k0 + 4); }
        if (bvalid){ b0 = ld4(Bp + k0); b1 = ld4(Bp + k0 + 4); }
        As[ak+0][ar] = f2tf32(a0.x); As[ak+1][ar] = f2tf32(a0.y);
        As[ak+2][ar] = f2tf32(a0.z); As[ak+3][ar] = f2tf32(a0.w);
        As[ak+4][ar] = f2tf32(a1.x); As[ak+5][ar] = f2tf32(a1.y);
        As[ak+6][ar] = f2tf32(a1.z); As[ak+7][ar] = f2tf32(a1.w);
        Bs[ak+0][ar] = f2tf32(b0.x); Bs[ak+1][ar] = f2tf32(b0.y);
        Bs[ak+2][ar] = f2tf32(b0.z); Bs[ak+3][ar] = f2tf32(b0.w);
        Bs[ak+4][ar] = f2tf32(b1.x); Bs[ak+5][ar] = f2tf32(b1.y);
        Bs[ak+6][ar] = f2tf32(b1.z); Bs[ak+7][ar] = f2tf32(b1.w);
        __syncthreads();

        #pragma unroll
        for (int ks = 0; ks < 16; ks += 8){
            float aR[4][4];
            float bR[4][2];
            #pragma unroll
            for (int mi = 0; mi < 4; mi++){
                int m0 = wm + mi*16 + g;
                aR[mi][0] = As[ks + t    ][m0    ];
                aR[mi][1] = As[ks + t    ][m0 + 8];
                aR[mi][2] = As[ks + t + 4][m0    ];
                aR[mi][3] = As[ks + t + 4][m0 + 8];
            }
            #pragma unroll
            for (int ni = 0; ni < 4; ni++){
                int n0 = wn + ni*8 + g;
                bR[ni][0] = Bs[ks + t    ][n0];
                bR[ni][1] = Bs[ks + t + 4][n0];
            }
            #pragma unroll
            for (int mi = 0; mi < 4; mi++)
                #pragma unroll
                for (int ni = 0; ni < 4; ni++)
                    mma_tf32(acc[mi][ni], aR[mi], bR[ni]);
        }
        __syncthreads();
    }

    #pragma unroll
    for (int mi = 0; mi < 4; mi++){
        int r0 = bm + wm + mi*16 + g;
        #pragma unroll
        for (int ni = 0; ni < 4; ni++){
            int c0 = bn + wn + ni*8 + 2*t;
            if (r0 < M)
                *reinterpret_cast<float2*>(C + (size_t)r0*ldc + c0)
                    = make_float2(acc[mi][ni][0], acc[mi][ni][1]);
            if (r0 + 8 < M)
                *reinterpret_cast<float2*>(C + (size_t)(r0+8)*ldc + c0)
                    = make_float2(acc[mi][ni][2], acc[mi][ni][3]);
        }
    }
}

// ---------------- layer-1 edge kernel: both heads fused, warp/edge ----------------
__global__ void k_edge1(const int* __restrict__ el, const int* __restrict__ eln,
                        const int* __restrict__ et, const int* __restrict__ etn,
                        const float* __restrict__ sd, const float* __restrict__ ss,
                        const float* __restrict__ sr,
                        const float* __restrict__ Ps, const float* __restrict__ R,
                        float* __restrict__ rs, float* __restrict__ S)
{
    int e = (blockIdx.x * blockDim.x + threadIdx.x) >> 5;
    int lane = threadIdx.x & 31;
    if (e >= ET) return;
    int dst, src, r0, r1 = -1;
    bool onehop = (e < E1);
    if (onehop){
        dst = el[e]; src = el[E1 + e]; r0 = et[e];
    } else {
        int i = e - E1;
        dst = eln[i]; src = eln[EN + i];
        r0 = etn[2*i]; r1 = etn[2*i + 1];
    }
    float ee0, ee1;
    if (lane == 0){
        float sr0 = onehop ? sr[r0]       : (sr[r0]       + sr[r1]);
        float sr1v= onehop ? sr[NREL+r0]  : (sr[NREL+r0]  + sr[NREL+r1]);
        float s0 = sd[dst]      + ss[src]      + sr0;
        float s1 = sd[NN + dst] + ss[NN + src] + sr1v;
        float lk0 = s0 > 0.f ? s0 : 0.2f * s0;
        float lk1 = s1 > 0.f ? s1 : 0.2f * s1;
        ee0 = expf(-lk0);
        ee1 = expf(-lk1);
        atomicAdd(rs + dst, ee0);
        atomicAdd(rs + NN + dst, ee1);
    }
    ee0 = __shfl_sync(0xffffffffu, ee0, 0);
    ee1 = __shfl_sync(0xffffffffu, ee1, 0);
    #pragma unroll
    for (int c0 = 0; c0 < 256; c0 += 128){
        int c = c0 + lane * 4;
        float ee = c0 ? ee1 : ee0;
        float4 p = ld4(Ps + (size_t)src * 256 + c);
        float4 r = ld4(R + (size_t)r0 * 256 + c);
        if (!onehop){
            float4 rb = ld4(R + (size_t)r1 * 256 + c);
            r.x += rb.x; r.y += rb.y; r.z += rb.z; r.w += rb.w;
        }
        red4(S + (size_t)dst * 256 + c,
             make_float4(ee*(p.x+r.x), ee*(p.y+r.y), ee*(p.z+r.z), ee*(p.w+r.w)));
    }
}

// ---------------- layer-2 edge kernel, warp/edge ----------------
__global__ void k_edge2(const int* __restrict__ el, const int* __restrict__ eln,
                        const int* __restrict__ et, const int* __restrict__ etn,
                        const float* __restrict__ sd, const float* __restrict__ ss,
                        const float* __restrict__ sr,
                        const float* __restrict__ Xs, const float* __restrict__ R,
                        float* __restrict__ rs, float* __restrict__ S)
{
    int e = (blockIdx.x * blockDim.x + threadIdx.x) >> 5;
    int lane = threadIdx.x & 31;
    if (e >= ET) return;
    int dst, src, r0, r1 = -1;
    bool onehop = (e < E1);
    if (onehop){
        dst = el[e]; src = el[E1 + e]; r0 = et[e];
    } else {
        int i = e - E1;
        dst = eln[i]; src = eln[EN + i];
        r0 = etn[2*i]; r1 = etn[2*i + 1];
    }
    float ee;
    if (lane == 0){
        float srv = onehop ? sr[r0] : (sr[r0] + sr[r1]);
        float s = sd[dst] + ss[src] + srv;
        float lk = s > 0.f ? s : 0.2f * s;
        ee = expf(-lk);
        atomicAdd(rs + dst, ee);
    }
    ee = __shfl_sync(0xffffffffu, ee, 0);
    #pragma unroll
    for (int c0 = 0; c0 < 256; c0 += 128){
        int c = c0 + lane * 4;
        float4 p = ld4(Xs + (size_t)src * 256 + c);
        float4 r = ld4(R + (size_t)r0 * 256 + c);
        if (!onehop){
            float4 rb = ld4(R + (size_t)r1 * 256 + c);
            r.x += rb.x; r.y += rb.y; r.z += rb.z; r.w += rb.w;
        }
        red4(S + (size_t)dst * 256 + c,
             make_float4(ee*(p.x+r.x), ee*(p.y+r.y), ee*(p.z+r.z), ee*(p.w+r.w)));
    }
}

// ---------------- layer-1 finalize ----------------
__global__ void k_fin1(const float* __restrict__ Pd, const float* __restrict__ S,
                       const float* __restrict__ rs, float* __restrict__ x)
{
    int n = (blockIdx.x * blockDim.x + threadIdx.x) >> 5;
    int lane = threadIdx.x & 31;
    if (n >= NN) return;
    int c = lane * 4;
    #pragma unroll
    for (int h = 0; h < 2; h++){
        float r  = rs[h*NN + n];
        float rc = (r == 0.f) ? 1e-12f : r;
        float4 pd = ld4(Pd + (size_t)n*512 + h*128 + c);
        float4 s  = ld4(S  + (size_t)n*256 + h*128 + c);
        float4 hv;
        hv.x = elu1(fmaf(r, pd.x, s.x) / rc);
        hv.y = elu1(fmaf(r, pd.y, s.y) / rc);
        hv.z = elu1(fmaf(r, pd.z, s.z) / rc);
        hv.w = elu1(fmaf(r, pd.w, s.w) / rc);
        st4(x + (size_t)n*256 + h*128 + c, hv);
    }
}

// ---------------- final outputs ----------------
__global__ void k_final(const float* __restrict__ Pd /*eup at +256*/,
                        const float* __restrict__ Xd,
                        const float* __restrict__ S2, const float* __restrict__ rs2,
                        const float* __restrict__ mask,
                        float* __restrict__ out1, float* __restrict__ out3)
{
    int n = (blockIdx.x * blockDim.x + threadIdx.x) >> 5;
    int lane = threadIdx.x & 31;
    if (n >= NN) return;
    float r  = rs2[n];
    float rc = (r == 0.f) ? 1e-12f : r;
    float mk = mask[n];
    float4 v1[2], v3[2];
    float ss1 = 0.f, ss3 = 0.f;
    #pragma unroll
    for (int q = 0; q < 2; q++){
        int c = q*128 + lane*4;
        float4 xd = ld4(Xd + (size_t)n*256 + c);
        float4 s2 = ld4(S2 + (size_t)n*256 + c);
        float4 e4 = ld4(Pd + (size_t)n*512 + 256 + c);
        float hr0 = fmaf(r, xd.x, s2.x);
        float hr1 = fmaf(r, xd.y, s2.y);
        float hr2 = fmaf(r, xd.z, s2.z);
        float hr3 = fmaf(r, xd.w, s2.w);
        float a0 = e4.x + mk * elu1(hr0 / rc);
        float a1 = e4.y + mk * elu1(hr1 / rc);
        float a2 = e4.z + mk * elu1(hr2 / rc);
        float a3 = e4.w + mk * elu1(hr3 / rc);
        float b0 = elu1(hr0), b1 = elu1(hr1), b2 = elu1(hr2), b3 = elu1(hr3);
        v1[q] = make_float4(a0, a1, a2, a3);
        v3[q] = make_float4(b0, b1, b2, b3);
        ss1 += a0*a0 + a1*a1 + a2*a2 + a3*a3;
        ss3 += b0*b0 + b1*b1 + b2*b2 + b3*b3;
    }
    ss1 = wred(ss1);
    ss3 = wred(ss3);
    float sc1 = 1.f / fmaxf(sqrtf(ss1), 1e-12f);
    float sc3 = 1.f / fmaxf(sqrtf(ss3), 1e-12f);
    #pragma unroll
    for (int q = 0; q < 2; q++){
        int c = q*128 + lane*4;
        st4(out1 + (size_t)n*256 + c, make_float4(v1[q].x*sc1, v1[q].y*sc1, v1[q].z*sc1, v1[q].w*sc1));
        st4(out3 + (size_t)n*256 + c, make_float4(v3[q].x*sc3, v3[q].y*sc3, v3[q].z*sc3, v3[q].w*sc3));
    }
}

// ---------------- host launch ----------------
static float* sym(const void* s){
    void* p = nullptr;
    cudaGetSymbolAddress(&p, s);
    return (float*)p;
}

extern "C" void kernel_launch(void* const* d_in, const int* in_sizes, int n_in,
                              void* d_out, int out_size)
{
    const float* ent    = (const float*)d_in[0];
    const float* rel    = (const float*)d_in[1];
    const float* a1     = (const float*)d_in[2];
    const float* a2_1   = (const float*)d_in[3];
    const float* W      = (const float*)d_in[4];
    const float* a_out  = (const float*)d_in[5];
    const float* a2_out = (const float*)d_in[6];
    const float* W_ent  = (const float*)d_in[7];
    const int*   bi     = (const int*)d_in[8];
    const int*   el     = (const int*)d_in[9];
    const int*   et     = (const int*)d_in[10];
    const int*   eln    = (const int*)d_in[11];
    const int*   etn    = (const int*)d_in[12];
    float* out = (float*)d_out;

    float* Z     = sym(g_Z);
    float* p_S1  = Z + OFF_S1;
    float* p_S2  = Z + OFF_S2;
    float* p_rs1 = Z + OFF_RS1;
    float* p_rs2 = Z + OFF_RS2;
    float* p_mask= Z + OFF_MASK;
    float* p_ent = sym(g_ent);
    float* p_Pd  = sym(g_Pd);  float* p_Ps  = sym(g_Ps);  float* p_R1 = sym(g_R1);
    float* p_x   = sym(g_x);   float* p_Xd  = sym(g_Xd);  float* p_Xs = sym(g_Xs);
    float* p_R2  = sym(g_R2);
    float* p_sd1 = sym(g_sd1); float* p_ss1 = sym(g_ss1); float* p_sr1= sym(g_sr1);
    float* p_sd2 = sym(g_sd2); float* p_ss2 = sym(g_ss2); float* p_sr2= sym(g_sr2);
    float* B1d = sym(g_B1d); float* B1s = sym(g_B1s); float* BR1 = sym(g_BR1);
    float* B2d = sym(g_B2d); float* B2s = sym(g_B2s); float* B3  = sym(g_B3);
    float* BW  = sym(g_BW);

    const int T = 256;
    const int GY = (NN + 127) / 128;         // 391
    const int GW = (NN*32 + T - 1) / T;      // warp-per-node grids
    const int GE = (ET*32 + T - 1) / T;      // warp-per-edge grids

    // 1: zero scratch
    k_zero4<<<4096, T>>>((float4*)Z, ZN/4);
    // 2: pack all weight slices
    k_packs<<<(512*128 + 3*256*128 + 3*256*256 + T-1)/T, T>>>(a1, a_out, W, W_ent,
        B1d, B1s, BR1, B2d, B2s, B3, BW);
    // 3: l2 normalize entities
    k_l2norm128<<<GW, T>>>(ent, p_ent);
    // 4: mask scatter
    k_setmask<<<16, T>>>(bi, p_mask);
    // 5: big layer-1 dst/eup GEMM  (profiled launch)
    gemm_tn_tf32<<<dim3(4, GY), T>>>(p_ent, 128, B1d, 128, p_Pd, 512, NN, 512, 128);
    // 6: Ps GEMM (compact, gathered later)
    gemm_tn_tf32<<<dim3(2, GY), T>>>(p_ent, 128, B1s, 128, p_Ps, 256, NN, 256, 128);
    // 7: relation projections (both heads)
    gemm_tn_tf32<<<dim3(2, 2), T>>>(rel, 128, BR1, 128, p_R1, 256, NREL, 256, 128);
    // 8: attention scalars (node side)
    k_dots1<<<GW, T>>>(p_Pd, p_Ps, a2_1, p_sd1, p_ss1);
    // 9-10: attention scalars (relation side)
    k_rowdot<<<(NREL*32 + T-1)/T, T>>>(p_R1,       256, 128, a2_1,       p_sr1,        NREL);
    k_rowdot<<<(NREL*32 + T-1)/T, T>>>(p_R1 + 128, 256, 128, a2_1 + 128, p_sr1 + NREL, NREL);
    // 11: fused 2-head edge scatter
    k_edge1<<<GE, T>>>(el, eln, et, etn, p_sd1, p_ss1, p_sr1, p_Ps, p_R1, p_rs1, p_S1);
    // 12: layer-1 finalize -> x
    k_fin1<<<GW, T>>>(p_Pd, p_S1, p_rs1, p_x);
    // 13: out_relation_1 = rel @ W
    gemm_tn_tf32<<<dim3(2, 2), T>>>(rel, 128, BW, 128, out + OREL, 256, NREL, 256, 128);
    // 14-15: layer-2 node projections
    gemm_tn_tf32<<<dim3(2, GY), T>>>(p_x, 256, B2d, 256, p_Xd, 256, NN, 256, 256);
    gemm_tn_tf32<<<dim3(2, GY), T>>>(p_x, 256, B2s, 256, p_Xs, 256, NN, 256, 256);
    // 16: layer-2 relation projection
    gemm_tn_tf32<<<dim3(2, 2), T>>>(out + OREL, 256, B3, 256, p_R2, 256, NREL, 256, 256);
    // 17: layer-2 attention scalars
    k_dots2<<<GW, T>>>(p_Xd, p_Xs, a2_out, p_sd2, p_ss2);
    // 18: relation-side scalar
    k_rowdot<<<(NREL*32 + T-1)/T, T>>>(p_R2, 256, 256, a2_out, p_sr2, NREL);
    // 19: layer-2 edge scatter
    k_edge2<<<GE, T>>>(el, eln, et, etn, p_sd2, p_ss2, p_sr2, p_Xs, p_R2, p_rs2, p_S2);
    // 20: final outputs
    k_final<<<GW, T>>>(p_Pd, p_Xd, p_S2, p_rs2, p_mask, out, out + O3);
}

// round 4
// speedup vs baseline: 2.3961x; 1.2934x over previous
#include <cuda_runtime.h>
#include <cuda_fp16.h>
#include <math.h>

#define NN   50000
#define E1   300000
#define EN   30000
#define ET   330000
#define OREL 12800000      // 50000*256
#define O3   12865536      // + 256*256
#define NREL 256

// ---------------- device scratch (static, allocation-free) ----------------
#define OFF_S1   0                       // [NN*256]
#define OFF_S2   (NN*256)                // [NN*256]
#define OFF_RS1  (2*NN*256)              // [2*NN]
#define OFF_RS2  (2*NN*256 + 2*NN)       // [NN]
#define OFF_MASK (2*NN*256 + 3*NN)       // [NN]
#define ZN       (2*NN*256 + 4*NN)
__device__ float g_Z[ZN];

__device__ __half g_entH[NN*128];
__device__ __half g_xH [NN*256];
__device__ __half g_orelH[256*256];
__device__ float g_Pd [NN*512];     // Pd_h0 | Pd_h1 | eup
__device__ float g_Ps [NN*256];
__device__ float g_R1 [NREL*256];
__device__ float g_Xd [NN*256];
__device__ float g_Xs [NN*256];
__device__ float g_R2 [NREL*256];
__device__ float g_sd1[2*NN];
__device__ float g_ss1[2*NN];
__device__ float g_sr1[2*NREL];
__device__ float g_sd2[NN];
__device__ float g_ss2[NN];
__device__ float g_sr2[NREL];
// packed fp16 B matrices ([N][K] row-major for TN gemm) + relH
__device__ __half hB1d[512*128];
__device__ __half hB1s[256*128];
__device__ __half hBR1[256*128];
__device__ __half hB2d[256*256];
__device__ __half hB2s[256*256];
__device__ __half hB3 [256*256];
__device__ __half hBW [256*128];
__device__ __half g_relH[256*128];

// ---------------- helpers ----------------
__device__ __forceinline__ float4 ld4(const float* p){ return *reinterpret_cast<const float4*>(p); }
__device__ __forceinline__ void   st4(float* p, float4 v){ *reinterpret_cast<float4*>(p) = v; }
__device__ __forceinline__ float  elu1(float x){ return x > 0.f ? x : expm1f(x); }
__device__ __forceinline__ float  wred(float v){
    #pragma unroll
    for (int o = 16; o; o >>= 1) v += __shfl_xor_sync(0xffffffffu, v, o);
    return v;
}
__device__ __forceinline__ void red4(float* p, float4 v){
    asm volatile("red.global.add.v4.f32 [%0], {%1, %2, %3, %4};"
                 :: "l"(p), "f"(v.x), "f"(v.y), "f"(v.z), "f"(v.w) : "memory");
}
__device__ __forceinline__ float dot4(float4 a, float4 b){
    return a.x*b.x + a.y*b.y + a.z*b.z + a.w*b.w;
}
__device__ __forceinline__ void mma_f16(float* c, const unsigned* a, const unsigned* b){
    asm volatile("mma.sync.aligned.m16n8k16.row.col.f32.f16.f16.f32 "
        "{%0,%1,%2,%3}, {%4,%5,%6,%7}, {%8,%9}, {%0,%1,%2,%3};"
        : "+f"(c[0]), "+f"(c[1]), "+f"(c[2]), "+f"(c[3])
        : "r"(a[0]), "r"(a[1]), "r"(a[2]), "r"(a[3]), "r"(b[0]), "r"(b[1]));
}

// ---------------- zero fill ----------------
__global__ void k_zero4(float4* __restrict__ p, int n4){
    int i  = blockIdx.x * blockDim.x + threadIdx.x;
    int st = gridDim.x * blockDim.x;
    float4 z = make_float4(0,0,0,0);
    for (; i < n4; i += st) p[i] = z;
}

// ---------------- pack all fp16 B matrices + relH ----------------
__global__ void k_packs(const float* __restrict__ a1, const float* __restrict__ a_out,
                        const float* __restrict__ W,  const float* __restrict__ W_ent,
                        const float* __restrict__ rel,
                        __half* __restrict__ B1d, __half* __restrict__ B1s,
                        __half* __restrict__ BR1, __half* __restrict__ B2d,
                        __half* __restrict__ B2s, __half* __restrict__ B3,
                        __half* __restrict__ BW,  __half* __restrict__ relH)
{
    int i = blockIdx.x * blockDim.x + threadIdx.x;
    if (i < 512*128){
        int r = i >> 7, k = i & 127;
        float v;
        if (r < 256){ int h = r >> 7, rr = r & 127; v = a1[h*128*384 + rr*384 + k]; }
        else        { v = W_ent[k*256 + (r - 256)]; }
        B1d[i] = __float2half_rn(v); return;
    }
    i -= 512*128;
    if (i < 256*128){
        int r = i >> 7, k = i & 127; int h = r >> 7, rr = r & 127;
        B1s[i] = __float2half_rn(a1[h*128*384 + rr*384 + 128 + k]); return;
    }
    i -= 256*128;
    if (i < 256*128){
        int r = i >> 7, k = i & 127; int h = r >> 7, rr = r & 127;
        BR1[i] = __float2half_rn(a1[h*128*384 + rr*384 + 256 + k]); return;
    }
    i -= 256*128;
    if (i < 256*256){ int r = i >> 8, k = i & 255; B2d[i] = __float2half_rn(a_out[r*768 + k]);       return; }
    i -= 256*256;
    if (i < 256*256){ int r = i >> 8, k = i & 255; B2s[i] = __float2half_rn(a_out[r*768 + 256 + k]); return; }
    i -= 256*256;
    if (i < 256*256){ int r = i >> 8, k = i & 255; B3[i]  = __float2half_rn(a_out[r*768 + 512 + k]); return; }
    i -= 256*256;
    if (i < 256*128){ int r = i >> 7, k = i & 127; BW[i]  = __float2half_rn(W[k*256 + r]);           return; }
    i -= 256*128;
    if (i < 256*128){ relH[i] = __float2half_rn(rel[i]); return; }
}

// ---------------- row l2-normalize, D=128, warp/row, fp16 out ----------------
__global__ void k_l2norm128(const float* __restrict__ in, __half* __restrict__ out){
    int n = (blockIdx.x * blockDim.x + threadIdx.x) >> 5;
    int lane = threadIdx.x & 31;
    if (n >= NN) return;
    int c = lane * 4;
    float4 v = ld4(in + (size_t)n*128 + c);
    float ss = dot4(v, v);
    ss = wred(ss);
    float s = 1.f / fmaxf(sqrtf(ss), 1e-12f);
    __half2 h0 = __floats2half2_rn(v.x*s, v.y*s);
    __half2 h1 = __floats2half2_rn(v.z*s, v.w*s);
    *reinterpret_cast<__half2*>(out + (size_t)n*128 + c)     = h0;
    *reinterpret_cast<__half2*>(out + (size_t)n*128 + c + 2) = h1;
}

// ---------------- mask ----------------
__global__ void k_setmask(const int* __restrict__ bi, float* __restrict__ mask){
    int i = blockIdx.x * blockDim.x + threadIdx.x;
    if (i < 4096) mask[bi[3*i + 2]] = 1.f;
}

// ---------------- generic strided rowdot ----------------
__global__ void k_rowdot(const float* __restrict__ A, int ld, int D,
                         const float* __restrict__ v, float* __restrict__ out, int M){
    int r = (blockIdx.x * blockDim.x + threadIdx.x) >> 5;
    int lane = threadIdx.x & 31;
    if (r >= M) return;
    float acc = 0.f;
    for (int c = lane * 4; c < D; c += 128)
        acc += dot4(ld4(A + (size_t)r*ld + c), ld4(v + c));
    acc = wred(acc);
    if (lane == 0) out[r] = acc;
}

// ---------------- fused layer-1 attention-scalar dots ----------------
__global__ void k_dots1(const float* __restrict__ Pd, const float* __restrict__ Ps,
                        const float* __restrict__ a2, float* __restrict__ sd, float* __restrict__ ss){
    int n = (blockIdx.x * blockDim.x + threadIdx.x) >> 5;
    int lane = threadIdx.x & 31;
    if (n >= NN) return;
    int c = lane * 4;
    float4 b0 = ld4(a2 + c), b1 = ld4(a2 + 128 + c);
    float d0 = dot4(ld4(Pd + (size_t)n*512 + c),       b0);
    float d1 = dot4(ld4(Pd + (size_t)n*512 + 128 + c), b1);
    float s0 = dot4(ld4(Ps + (size_t)n*256 + c),       b0);
    float s1 = dot4(ld4(Ps + (size_t)n*256 + 128 + c), b1);
    d0 = wred(d0); d1 = wred(d1); s0 = wred(s0); s1 = wred(s1);
    if (lane == 0){ sd[n] = d0; sd[NN + n] = d1; ss[n] = s0; ss[NN + n] = s1; }
}

// ---------------- fused layer-2 attention-scalar dots ----------------
__global__ void k_dots2(const float* __restrict__ Xd, const float* __restrict__ Xs,
                        const float* __restrict__ a2, float* __restrict__ sd, float* __restrict__ ss){
    int n = (blockIdx.x * blockDim.x + threadIdx.x) >> 5;
    int lane = threadIdx.x & 31;
    if (n >= NN) return;
    float d = 0.f, s = 0.f;
    #pragma unroll
    for (int c0 = 0; c0 < 256; c0 += 128){
        int c = c0 + lane*4;
        float4 b = ld4(a2 + c);
        d += dot4(ld4(Xd + (size_t)n*256 + c), b);
        s += dot4(ld4(Xs + (size_t)n*256 + c), b);
    }
    d = wred(d); s = wred(s);
    if (lane == 0){ sd[n] = d; ss[n] = s; }
}

// ---------------- FP16 tensor-core GEMM (TN): C[M,N] = A[M,K] * B[N,K]^T ----------------
// A half row-major, B half row-major [N,K], C fp32 row-major, optional Ch half copy.
// Requires K%32==0, N%128==0 and covered exactly by grid.x.
#define SA 40   // smem stride (halves); (g*20+t) mod 32 all distinct -> conflict-free
__global__ __launch_bounds__(256, 2)
void gemm_tn_f16(const __half* __restrict__ A, int lda,
                 const __half* __restrict__ B, int ldb,
                 float* __restrict__ C, int ldc,
                 __half* __restrict__ Ch,
                 int M, int N, int K)
{
    __shared__ __half As[128*SA];
    __shared__ __half Bs[128*SA];
    const int bm = blockIdx.y * 128;
    const int bn = blockIdx.x * 128;
    const int tid  = threadIdx.x;
    const int warp = tid >> 5;
    const int lane = tid & 31;
    const int wm = (warp & 1) * 64;
    const int wn = (warp >> 1) * 32;
    const int g = lane >> 2;
    const int t = lane & 3;

    float acc[4][4][4];
    #pragma unroll
    for (int i = 0; i < 4; i++)
        #pragma unroll
        for (int j = 0; j < 4; j++)
            #pragma unroll
            for (int q = 0; q < 4; q++) acc[i][j][q] = 0.f;

    const int row  = tid >> 1;
    const int koff = (tid & 1) * 16;
    const bool avalid = (bm + row) < M;
    const __half* Ap = A + (size_t)(bm + row) * lda + koff;
    const __half* Bp = B + (size_t)(bn + row) * ldb + koff;
    const uint4 z4 = make_uint4(0,0,0,0);

    for (int k0 = 0; k0 < K; k0 += 32){
        uint4 av0 = z4, av1 = z4;
        if (avalid){
            av0 = *reinterpret_cast<const uint4*>(Ap + k0);
            av1 = *reinterpret_cast<const uint4*>(Ap + k0 + 8);
        }
        uint4 bv0 = *reinterpret_cast<const uint4*>(Bp + k0);
        uint4 bv1 = *reinterpret_cast<const uint4*>(Bp + k0 + 8);
        *reinterpret_cast<uint4*>(&As[row*SA + koff])     = av0;
        *reinterpret_cast<uint4*>(&As[row*SA + koff + 8]) = av1;
        *reinterpret_cast<uint4*>(&Bs[row*SA + koff])     = bv0;
        *reinterpret_cast<uint4*>(&Bs[row*SA + koff + 8]) = bv1;
        __syncthreads();

        #pragma unroll
        for (int ks = 0; ks < 2; ks++){
            unsigned aR[4][4];
            unsigned bR[4][2];
            const int kb = ks*16 + 2*t;
            #pragma unroll
            for (int mi = 0; mi < 4; mi++){
                int m0 = (wm + mi*16 + g)*SA + kb;
                aR[mi][0] = *reinterpret_cast<const unsigned*>(&As[m0]);
                aR[mi][1] = *reinterpret_cast<const unsigned*>(&As[m0 + 8*SA]);
                aR[mi][2] = *reinterpret_cast<const unsigned*>(&As[m0 + 8]);
                aR[mi][3] = *reinterpret_cast<const unsigned*>(&As[m0 + 8*SA + 8]);
            }
            #pragma unroll
            for (int ni = 0; ni < 4; ni++){
                int n0 = (wn + ni*8 + g)*SA + kb;
                bR[ni][0] = *reinterpret_cast<const unsigned*>(&Bs[n0]);
                bR[ni][1] = *reinterpret_cast<const unsigned*>(&Bs[n0 + 8]);
            }
            #pragma unroll
            for (int mi = 0; mi < 4; mi++)
                #pragma unroll
                for (int ni = 0; ni < 4; ni++)
                    mma_f16(acc[mi][ni], aR[mi], bR[ni]);
        }
        __syncthreads();
    }

    #pragma unroll
    for (int mi = 0; mi < 4; mi++){
        int r0 = bm + wm + mi*16 + g;
        #pragma unroll
        for (int ni = 0; ni < 4; ni++){
            int c0 = bn + wn + ni*8 + 2*t;
            if (r0 < M){
                *reinterpret_cast<float2*>(C + (size_t)r0*ldc + c0)
                    = make_float2(acc[mi][ni][0], acc[mi][ni][1]);
                if (Ch) *reinterpret_cast<__half2*>(Ch + (size_t)r0*ldc + c0)
                    = __floats2half2_rn(acc[mi][ni][0], acc[mi][ni][1]);
            }
            if (r0 + 8 < M){
                *reinterpret_cast<float2*>(C + (size_t)(r0+8)*ldc + c0)
                    = make_float2(acc[mi][ni][2], acc[mi][ni][3]);
                if (Ch) *reinterpret_cast<__half2*>(Ch + (size_t)(r0+8)*ldc + c0)
                    = __floats2half2_rn(acc[mi][ni][2], acc[mi][ni][3]);
            }
        }
    }
}

// ---------------- layer-1 edge kernel: both heads fused, warp/edge ----------------
__global__ void k_edge1(const int* __restrict__ el, const int* __restrict__ eln,
                        const int* __restrict__ et, const int* __restrict__ etn,
                        const float* __restrict__ sd, const float* __restrict__ ss,
                        const float* __restrict__ sr,
                        const float* __restrict__ Ps, const float* __restrict__ R,
                        float* __restrict__ rs, float* __restrict__ S)
{
    int e = (blockIdx.x * blockDim.x + threadIdx.x) >> 5;
    int lane = threadIdx.x & 31;
    if (e >= ET) return;
    int dst, src, r0, r1 = -1;
    bool onehop = (e < E1);
    if (onehop){
        dst = el[e]; src = el[E1 + e]; r0 = et[e];
    } else {
        int i = e - E1;
        dst = eln[i]; src = eln[EN + i];
        r0 = etn[2*i]; r1 = etn[2*i + 1];
    }
    float ee0, ee1;
    if (lane == 0){
        float sr0 = onehop ? sr[r0]       : (sr[r0]       + sr[r1]);
        float sr1v= onehop ? sr[NREL+r0]  : (sr[NREL+r0]  + sr[NREL+r1]);
        float s0 = sd[dst]      + ss[src]      + sr0;
        float s1 = sd[NN + dst] + ss[NN + src] + sr1v;
        float lk0 = s0 > 0.f ? s0 : 0.2f * s0;
        float lk1 = s1 > 0.f ? s1 : 0.2f * s1;
        ee0 = expf(-lk0);
        ee1 = expf(-lk1);
        atomicAdd(rs + dst, ee0);
        atomicAdd(rs + NN + dst, ee1);
    }
    ee0 = __shfl_sync(0xffffffffu, ee0, 0);
    ee1 = __shfl_sync(0xffffffffu, ee1, 0);
    #pragma unroll
    for (int c0 = 0; c0 < 256; c0 += 128){
        int c = c0 + lane * 4;
        float ee = c0 ? ee1 : ee0;
        float4 p = ld4(Ps + (size_t)src * 256 + c);
        float4 r = ld4(R + (size_t)r0 * 256 + c);
        if (!onehop){
            float4 rb = ld4(R + (size_t)r1 * 256 + c);
            r.x += rb.x; r.y += rb.y; r.z += rb.z; r.w += rb.w;
        }
        red4(S + (size_t)dst * 256 + c,
             make_float4(ee*(p.x+r.x), ee*(p.y+r.y), ee*(p.z+r.z), ee*(p.w+r.w)));
    }
}

// ---------------- layer-2 edge kernel, warp/edge ----------------
__global__ void k_edge2(const int* __restrict__ el, const int* __restrict__ eln,
                        const int* __restrict__ et, const int* __restrict__ etn,
                        const float* __restrict__ sd, const float* __restrict__ ss,
                        const float* __restrict__ sr,
                        const float* __restrict__ Xs, const float* __restrict__ R,
                        float* __restrict__ rs, float* __restrict__ S)
{
    int e = (blockIdx.x * blockDim.x + threadIdx.x) >> 5;
    int lane = threadIdx.x & 31;
    if (e >= ET) return;
    int dst, src, r0, r1 = -1;
    bool onehop = (e < E1);
    if (onehop){
        dst = el[e]; src = el[E1 + e]; r0 = et[e];
    } else {
        int i = e - E1;
        dst = eln[i]; src = eln[EN + i];
        r0 = etn[2*i]; r1 = etn[2*i + 1];
    }
    float ee;
    if (lane == 0){
        float srv = onehop ? sr[r0] : (sr[r0] + sr[r1]);
        float s = sd[dst] + ss[src] + srv;
        float lk = s > 0.f ? s : 0.2f * s;
        ee = expf(-lk);
        atomicAdd(rs + dst, ee);
    }
    ee = __shfl_sync(0xffffffffu, ee, 0);
    #pragma unroll
    for (int c0 = 0; c0 < 256; c0 += 128){
        int c = c0 + lane * 4;
        float4 p = ld4(Xs + (size_t)src * 256 + c);
        float4 r = ld4(R + (size_t)r0 * 256 + c);
        if (!onehop){
            float4 rb = ld4(R + (size_t)r1 * 256 + c);
            r.x += rb.x; r.y += rb.y; r.z += rb.z; r.w += rb.w;
        }
        red4(S + (size_t)dst * 256 + c,
             make_float4(ee*(p.x+r.x), ee*(p.y+r.y), ee*(p.z+r.z), ee*(p.w+r.w)));
    }
}

// ---------------- layer-1 finalize -> x (fp16) ----------------
__global__ void k_fin1(const float* __restrict__ Pd, const float* __restrict__ S,
                       const float* __restrict__ rs, __half* __restrict__ x)
{
    int n = (blockIdx.x * blockDim.x + threadIdx.x) >> 5;
    int lane = threadIdx.x & 31;
    if (n >= NN) return;
    int c = lane * 4;
    #pragma unroll
    for (int h = 0; h < 2; h++){
        float r  = rs[h*NN + n];
        float rc = (r == 0.f) ? 1e-12f : r;
        float4 pd = ld4(Pd + (size_t)n*512 + h*128 + c);
        float4 s  = ld4(S  + (size_t)n*256 + h*128 + c);
        float h0 = elu1(fmaf(r, pd.x, s.x) / rc);
        float h1 = elu1(fmaf(r, pd.y, s.y) / rc);
        float h2 = elu1(fmaf(r, pd.z, s.z) / rc);
        float h3 = elu1(fmaf(r, pd.w, s.w) / rc);
        __half* xp = x + (size_t)n*256 + h*128 + c;
        *reinterpret_cast<__half2*>(xp)     = __floats2half2_rn(h0, h1);
        *reinterpret_cast<__half2*>(xp + 2) = __floats2half2_rn(h2, h3);
    }
}

// ---------------- final outputs ----------------
__global__ void k_final(const float* __restrict__ Pd /*eup at +256*/,
                        const float* __restrict__ Xd,
                        const float* __restrict__ S2, const float* __restrict__ rs2,
                        const float* __restrict__ mask,
                        float* __restrict__ out1, float* __restrict__ out3)
{
    int n = (blockIdx.x * blockDim.x + threadIdx.x) >> 5;
    int lane = threadIdx.x & 31;
    if (n >= NN) return;
    float r  = rs2[n];
    float rc = (r == 0.f) ? 1e-12f : r;
    float mk = mask[n];
    float4 v1[2], v3[2];
    float ss1 = 0.f, ss3 = 0.f;
    #pragma unroll
    for (int q = 0; q < 2; q++){
        int c = q*128 + lane*4;
        float4 xd = ld4(Xd + (size_t)n*256 + c);
        float4 s2 = ld4(S2 + (size_t)n*256 + c);
        float4 e4 = ld4(Pd + (size_t)n*512 + 256 + c);
        float hr0 = fmaf(r, xd.x, s2.x);
        float hr1 = fmaf(r, xd.y, s2.y);
        float hr2 = fmaf(r, xd.z, s2.z);
        float hr3 = fmaf(r, xd.w, s2.w);
        float a0 = e4.x + mk * elu1(hr0 / rc);
        float a1 = e4.y + mk * elu1(hr1 / rc);
        float a2 = e4.z + mk * elu1(hr2 / rc);
        float a3 = e4.w + mk * elu1(hr3 / rc);
        float b0 = elu1(hr0), b1 = elu1(hr1), b2 = elu1(hr2), b3 = elu1(hr3);
        v1[q] = make_float4(a0, a1, a2, a3);
        v3[q] = make_float4(b0, b1, b2, b3);
        ss1 += a0*a0 + a1*a1 + a2*a2 + a3*a3;
        ss3 += b0*b0 + b1*b1 + b2*b2 + b3*b3;
    }
    ss1 = wred(ss1);
    ss3 = wred(ss3);
    float sc1 = 1.f / fmaxf(sqrtf(ss1), 1e-12f);
    float sc3 = 1.f / fmaxf(sqrtf(ss3), 1e-12f);
    #pragma unroll
    for (int q = 0; q < 2; q++){
        int c = q*128 + lane*4;
        st4(out1 + (size_t)n*256 + c, make_float4(v1[q].x*sc1, v1[q].y*sc1, v1[q].z*sc1, v1[q].w*sc1));
        st4(out3 + (size_t)n*256 + c, make_float4(v3[q].x*sc3, v3[q].y*sc3, v3[q].z*sc3, v3[q].w*sc3));
    }
}

// ---------------- host launch ----------------
static void* symv(const void* s){
    void* p = nullptr;
    cudaGetSymbolAddress(&p, s);
    return p;
}

extern "C" void kernel_launch(void* const* d_in, const int* in_sizes, int n_in,
                              void* d_out, int out_size)
{
    const float* ent    = (const float*)d_in[0];
    const float* rel    = (const float*)d_in[1];
    const float* a1     = (const float*)d_in[2];
    const float* a2_1   = (const float*)d_in[3];
    const float* W      = (const float*)d_in[4];
    const float* a_out  = (const float*)d_in[5];
    const float* a2_out = (const float*)d_in[6];
    const float* W_ent  = (const float*)d_in[7];
    const int*   bi     = (const int*)d_in[8];
    const int*   el     = (const int*)d_in[9];
    const int*   et     = (const int*)d_in[10];
    const int*   eln    = (const int*)d_in[11];
    const int*   etn    = (const int*)d_in[12];
    float* out = (float*)d_out;

    float* Z      = (float*)symv(g_Z);
    float* p_S1   = Z + OFF_S1;
    float* p_S2   = Z + OFF_S2;
    float* p_rs1  = Z + OFF_RS1;
    float* p_rs2  = Z + OFF_RS2;
    float* p_mask = Z + OFF_MASK;
    __half* entH  = (__half*)symv(g_entH);
    __half* xH    = (__half*)symv(g_xH);
    __half* orelH = (__half*)symv(g_orelH);
    float* p_Pd = (float*)symv(g_Pd);  float* p_Ps = (float*)symv(g_Ps);
    float* p_R1 = (float*)symv(g_R1);  float* p_Xd = (float*)symv(g_Xd);
    float* p_Xs = (float*)symv(g_Xs);  float* p_R2 = (float*)symv(g_R2);
    float* p_sd1= (float*)symv(g_sd1); float* p_ss1= (float*)symv(g_ss1);
    float* p_sr1= (float*)symv(g_sr1); float* p_sd2= (float*)symv(g_sd2);
    float* p_ss2= (float*)symv(g_ss2); float* p_sr2= (float*)symv(g_sr2);
    __half* B1d = (__half*)symv(hB1d); __half* B1s = (__half*)symv(hB1s);
    __half* BR1 = (__half*)symv(hBR1); __half* B2d = (__half*)symv(hB2d);
    __half* B2s = (__half*)symv(hB2s); __half* B3  = (__half*)symv(hB3);
    __half* BW  = (__half*)symv(hBW);  __half* relH= (__half*)symv(g_relH);

    const int T = 256;
    const int GY = (NN + 127) / 128;
    const int GW = (NN*32 + T - 1) / T;
    const int GE = (ET*32 + T - 1) / T;
    const int NPACK = 512*128 + 2*256*128 + 3*256*256 + 2*256*128;

    // 1: zero scratch
    k_zero4<<<4096, T>>>((float4*)Z, ZN/4);
    // 2: pack fp16 weights + relH
    k_packs<<<(NPACK + T-1)/T, T>>>(a1, a_out, W, W_ent, rel,
                                    B1d, B1s, BR1, B2d, B2s, B3, BW, relH);
    // 3: l2 normalize entities -> fp16
    k_l2norm128<<<GW, T>>>(ent, entH);
    // 4: big layer-1 dst/eup GEMM  (profiled launch)
    gemm_tn_f16<<<dim3(4, GY), T>>>(entH, 128, B1d, 128, p_Pd, 512, nullptr, NN, 512, 128);
    // 5: Ps GEMM
    gemm_tn_f16<<<dim3(2, GY), T>>>(entH, 128, B1s, 128, p_Ps, 256, nullptr, NN, 256, 128);
    // 6: relation projections (both heads)
    gemm_tn_f16<<<dim3(2, 2), T>>>(relH, 128, BR1, 128, p_R1, 256, nullptr, NREL, 256, 128);
    // 7: attention scalars (node side)
    k_dots1<<<GW, T>>>(p_Pd, p_Ps, a2_1, p_sd1, p_ss1);
    // 8-9: attention scalars (relation side)
    k_rowdot<<<(NREL*32 + T-1)/T, T>>>(p_R1,       256, 128, a2_1,       p_sr1,        NREL);
    k_rowdot<<<(NREL*32 + T-1)/T, T>>>(p_R1 + 128, 256, 128, a2_1 + 128, p_sr1 + NREL, NREL);
    // 10: fused 2-head edge scatter
    k_edge1<<<GE, T>>>(el, eln, et, etn, p_sd1, p_ss1, p_sr1, p_Ps, p_R1, p_rs1, p_S1);
    // 11: layer-1 finalize -> xH
    k_fin1<<<GW, T>>>(p_Pd, p_S1, p_rs1, xH);
    // 12: out_relation_1 = rel @ W (fp32 out + fp16 copy)
    gemm_tn_f16<<<dim3(2, 2), T>>>(relH, 128, BW, 128, out + OREL, 256, orelH, NREL, 256, 128);
    // 13-14: layer-2 node projections
    gemm_tn_f16<<<dim3(2, GY), T>>>(xH, 256, B2d, 256, p_Xd, 256, nullptr, NN, 256, 256);
    gemm_tn_f16<<<dim3(2, GY), T>>>(xH, 256, B2s, 256, p_Xs, 256, nullptr, NN, 256, 256);
    // 15: layer-2 relation projection
    gemm_tn_f16<<<dim3(2, 2), T>>>(orelH, 256, B3, 256, p_R2, 256, nullptr, NREL, 256, 256);
    // 16: layer-2 attention scalars
    k_dots2<<<GW, T>>>(p_Xd, p_Xs, a2_out, p_sd2, p_ss2);
    // 17: relation-side scalar
    k_rowdot<<<(NREL*32 + T-1)/T, T>>>(p_R2, 256, 256, a2_out, p_sr2, NREL);
    // 18: mask scatter
    k_setmask<<<16, T>>>(bi, p_mask);
    // 19: layer-2 edge scatter
    k_edge2<<<GE, T>>>(el, eln, et, etn, p_sd2, p_ss2, p_sr2, p_Xs, p_R2, p_rs2, p_S2);
    // 20: final outputs
    k_final<<<GW, T>>>(p_Pd, p_Xd, p_S2, p_rs2, p_mask, out, out + O3);
}

// round 5
// speedup vs baseline: 2.6376x; 1.1008x over previous
#include <cuda_runtime.h>
#include <cuda_fp16.h>
#include <math.h>

#define NN   50000
#define E1   300000
#define EN   30000
#define ET   330000
#define OREL 12800000      // 50000*256
#define O3   12865536      // + 256*256
#define NREL 256

// ---------------- device scratch (static, allocation-free) ----------------
#define OFF_S1   0                       // [NN*256]
#define OFF_S2   (NN*256)                // [NN*256]
#define OFF_RS1  (2*NN*256)              // [2*NN]
#define OFF_RS2  (2*NN*256 + 2*NN)       // [NN]
#define OFF_MASK (2*NN*256 + 3*NN)       // [NN]
#define ZN       (2*NN*256 + 4*NN)
__device__ float g_Z[ZN];

__device__ __half g_entH[NN*128];
__device__ __half g_xH [NN*256];
__device__ __half g_orelH[256*256];
__device__ float g_Pd [NN*512];     // Pd_h0 | Pd_h1 | eup
__device__ float g_Ps [NN*256];
__device__ float g_R1 [NREL*256];
__device__ float g_Xd [NN*256];
__device__ float g_Xs [NN*256];
__device__ float g_R2 [NREL*256];
__device__ float g_sd1[2*NN];
__device__ float g_ss1[2*NN];
__device__ float g_sr1[2*NREL];
__device__ float g_sd2[NN];
__device__ float g_ss2[NN];
__device__ float g_sr2[NREL];
// packed fp16 B matrices ([N][K] row-major for TN gemm) + relH
__device__ __half hB1d[512*128];
__device__ __half hB1s[256*128];
__device__ __half hBR1[256*128];
__device__ __half hB2d[256*256];
__device__ __half hB2s[256*256];
__device__ __half hB3 [256*256];
__device__ __half hBW [256*128];
__device__ __half g_relH[256*128];

// ---------------- helpers ----------------
__device__ __forceinline__ float4 ld4(const float* p){ return *reinterpret_cast<const float4*>(p); }
__device__ __forceinline__ void   st4(float* p, float4 v){ *reinterpret_cast<float4*>(p) = v; }
__device__ __forceinline__ float  elu1(float x){ return x > 0.f ? x : expm1f(x); }
__device__ __forceinline__ float  wred(float v){
    #pragma unroll
    for (int o = 16; o; o >>= 1) v += __shfl_xor_sync(0xffffffffu, v, o);
    return v;
}
__device__ __forceinline__ void red4(float* p, float4 v){
    asm volatile("red.global.add.v4.f32 [%0], {%1, %2, %3, %4};"
                 :: "l"(p), "f"(v.x), "f"(v.y), "f"(v.z), "f"(v.w) : "memory");
}
__device__ __forceinline__ float dot4(float4 a, float4 b){
    return a.x*b.x + a.y*b.y + a.z*b.z + a.w*b.w;
}
__device__ __forceinline__ void mma_f16(float* c, const unsigned* a, const unsigned* b){
    asm volatile("mma.sync.aligned.m16n8k16.row.col.f32.f16.f16.f32 "
        "{%0,%1,%2,%3}, {%4,%5,%6,%7}, {%8,%9}, {%0,%1,%2,%3};"
        : "+f"(c[0]), "+f"(c[1]), "+f"(c[2]), "+f"(c[3])
        : "r"(a[0]), "r"(a[1]), "r"(a[2]), "r"(a[3]), "r"(b[0]), "r"(b[1]));
}
__device__ __forceinline__ void ldm4(unsigned& r0, unsigned& r1, unsigned& r2, unsigned& r3, unsigned a){
    asm volatile("ldmatrix.sync.aligned.m8n8.x4.shared.b16 {%0,%1,%2,%3}, [%4];"
        : "=r"(r0), "=r"(r1), "=r"(r2), "=r"(r3) : "r"(a));
}
__device__ __forceinline__ void cpasync16(unsigned dst, const void* src, int sz){
    asm volatile("cp.async.cg.shared.global [%0], [%1], 16, %2;"
                 :: "r"(dst), "l"(src), "r"(sz) : "memory");
}
__device__ __forceinline__ void cp_commit(){ asm volatile("cp.async.commit_group;" ::: "memory"); }
__device__ __forceinline__ void cp_wait1(){ asm volatile("cp.async.wait_group 1;" ::: "memory"); }

// ---------------- zero fill ----------------
__global__ void k_zero4(float4* __restrict__ p, int n4){
    int i  = blockIdx.x * blockDim.x + threadIdx.x;
    int st = gridDim.x * blockDim.x;
    float4 z = make_float4(0,0,0,0);
    for (; i < n4; i += st) p[i] = z;
}

// ---------------- pack all fp16 B matrices + relH ----------------
__global__ void k_packs(const float* __restrict__ a1, const float* __restrict__ a_out,
                        const float* __restrict__ W,  const float* __restrict__ W_ent,
                        const float* __restrict__ rel,
                        __half* __restrict__ B1d, __half* __restrict__ B1s,
                        __half* __restrict__ BR1, __half* __restrict__ B2d,
                        __half* __restrict__ B2s, __half* __restrict__ B3,
                        __half* __restrict__ BW,  __half* __restrict__ relH)
{
    int i = blockIdx.x * blockDim.x + threadIdx.x;
    if (i < 512*128){
        int r = i >> 7, k = i & 127;
        float v;
        if (r < 256){ int h = r >> 7, rr = r & 127; v = a1[h*128*384 + rr*384 + k]; }
        else        { v = W_ent[k*256 + (r - 256)]; }
        B1d[i] = __float2half_rn(v); return;
    }
    i -= 512*128;
    if (i < 256*128){
        int r = i >> 7, k = i & 127; int h = r >> 7, rr = r & 127;
        B1s[i] = __float2half_rn(a1[h*128*384 + rr*384 + 128 + k]); return;
    }
    i -= 256*128;
    if (i < 256*128){
        int r = i >> 7, k = i & 127; int h = r >> 7, rr = r & 127;
        BR1[i] = __float2half_rn(a1[h*128*384 + rr*384 + 256 + k]); return;
    }
    i -= 256*128;
    if (i < 256*256){ int r = i >> 8, k = i & 255; B2d[i] = __float2half_rn(a_out[r*768 + k]);       return; }
    i -= 256*256;
    if (i < 256*256){ int r = i >> 8, k = i & 255; B2s[i] = __float2half_rn(a_out[r*768 + 256 + k]); return; }
    i -= 256*256;
    if (i < 256*256){ int r = i >> 8, k = i & 255; B3[i]  = __float2half_rn(a_out[r*768 + 512 + k]); return; }
    i -= 256*256;
    if (i < 256*128){ int r = i >> 7, k = i & 127; BW[i]  = __float2half_rn(W[k*256 + r]);           return; }
    i -= 256*128;
    if (i < 256*128){ relH[i] = __float2half_rn(rel[i]); return; }
}

// ---------------- row l2-normalize, D=128, warp/row, fp16 out ----------------
__global__ void k_l2norm128(const float* __restrict__ in, __half* __restrict__ out){
    int n = (blockIdx.x * blockDim.x + threadIdx.x) >> 5;
    int lane = threadIdx.x & 31;
    if (n >= NN) return;
    int c = lane * 4;
    float4 v = ld4(in + (size_t)n*128 + c);
    float ss = dot4(v, v);
    ss = wred(ss);
    float s = 1.f / fmaxf(sqrtf(ss), 1e-12f);
    __half2 h0 = __floats2half2_rn(v.x*s, v.y*s);
    __half2 h1 = __floats2half2_rn(v.z*s, v.w*s);
    *reinterpret_cast<__half2*>(out + (size_t)n*128 + c)     = h0;
    *reinterpret_cast<__half2*>(out + (size_t)n*128 + c + 2) = h1;
}

// ---------------- mask ----------------
__global__ void k_setmask(const int* __restrict__ bi, float* __restrict__ mask){
    int i = blockIdx.x * blockDim.x + threadIdx.x;
    if (i < 4096) mask[bi[3*i + 2]] = 1.f;
}

// ---------------- generic strided rowdot ----------------
__global__ void k_rowdot(const float* __restrict__ A, int ld, int D,
                         const float* __restrict__ v, float* __restrict__ out, int M){
    int r = (blockIdx.x * blockDim.x + threadIdx.x) >> 5;
    int lane = threadIdx.x & 31;
    if (r >= M) return;
    float acc = 0.f;
    for (int c = lane * 4; c < D; c += 128)
        acc += dot4(ld4(A + (size_t)r*ld + c), ld4(v + c));
    acc = wred(acc);
    if (lane == 0) out[r] = acc;
}

// ---------------- fused layer-1 attention-scalar dots ----------------
__global__ void k_dots1(const float* __restrict__ Pd, const float* __restrict__ Ps,
                        const float* __restrict__ a2, float* __restrict__ sd, float* __restrict__ ss){
    int n = (blockIdx.x * blockDim.x + threadIdx.x) >> 5;
    int lane = threadIdx.x & 31;
    if (n >= NN) return;
    int c = lane * 4;
    float4 b0 = ld4(a2 + c), b1 = ld4(a2 + 128 + c);
    float d0 = dot4(ld4(Pd + (size_t)n*512 + c),       b0);
    float d1 = dot4(ld4(Pd + (size_t)n*512 + 128 + c), b1);
    float s0 = dot4(ld4(Ps + (size_t)n*256 + c),       b0);
    float s1 = dot4(ld4(Ps + (size_t)n*256 + 128 + c), b1);
    d0 = wred(d0); d1 = wred(d1); s0 = wred(s0); s1 = wred(s1);
    if (lane == 0){ sd[n] = d0; sd[NN + n] = d1; ss[n] = s0; ss[NN + n] = s1; }
}

// ---------------- fused layer-2 attention-scalar dots ----------------
__global__ void k_dots2(const float* __restrict__ Xd, const float* __restrict__ Xs,
                        const float* __restrict__ a2, float* __restrict__ sd, float* __restrict__ ss){
    int n = (blockIdx.x * blockDim.x + threadIdx.x) >> 5;
    int lane = threadIdx.x & 31;
    if (n >= NN) return;
    float d = 0.f, s = 0.f;
    #pragma unroll
    for (int c0 = 0; c0 < 256; c0 += 128){
        int c = c0 + lane*4;
        float4 b = ld4(a2 + c);
        d += dot4(ld4(Xd + (size_t)n*256 + c), b);
        s += dot4(ld4(Xs + (size_t)n*256 + c), b);
    }
    d = wred(d); s = wred(s);
    if (lane == 0){ sd[n] = d; ss[n] = s; }
}

// ---------------- FP16 tensor-core GEMM (TN), ldmatrix + cp.async double-buffer ----
// C[M,N] = A[M,K] * B[N,K]^T.  A,B half row-major; C fp32; optional Ch half copy.
// Requires K%32==0, N%128==0 covered by grid.x.
#define SA 40                    // smem row stride in halves
#define MATB (128*SA*2)          // bytes per matrix tile (10240)
#define STB  (2*MATB)            // bytes per stage (A+B)
__global__ __launch_bounds__(256, 2)
void gemm_tn_f16(const __half* __restrict__ A, int lda,
                 const __half* __restrict__ B, int ldb,
                 float* __restrict__ C, int ldc,
                 __half* __restrict__ Ch,
                 int M, int N, int K)
{
    __shared__ __half sm[2*2*128*SA];
    const unsigned sbase = (unsigned)__cvta_generic_to_shared(sm);
    const int bm = blockIdx.y * 128;
    const int bn = blockIdx.x * 128;
    const int tid  = threadIdx.x;
    const int warp = tid >> 5;
    const int lane = tid & 31;
    const int wm = (warp & 1) * 64;
    const int wn = (warp >> 1) * 32;
    const int g = lane >> 2;
    const int t = lane & 3;

    float acc[4][4][4];
    #pragma unroll
    for (int i = 0; i < 4; i++)
        #pragma unroll
        for (int j = 0; j < 4; j++)
            #pragma unroll
            for (int q = 0; q < 4; q++) acc[i][j][q] = 0.f;

    // ---- tile load setup (per thread: 2x16B for A, 2x16B for B) ----
    const int row  = tid >> 1;
    const int koff = (tid & 1) * 16;
    const __half* Ap = A + (size_t)(bm + row) * lda + koff;
    const __half* Bp = B + (size_t)(bn + row) * ldb + koff;
    const unsigned dA = sbase + (unsigned)((row*SA + koff) * 2);
    const unsigned dB = dA + MATB;
    const int szA = ((bm + row) < M) ? 16 : 0;

    // ---- ldmatrix lane offsets (bytes within a stage's A / B tile) ----
    const unsigned laneA = (unsigned)(((lane & 7) + ((lane >> 3) & 1) * 8) * SA
                                      + ((lane >> 4) & 1) * 8) * 2;
    const unsigned laneB = (unsigned)(((lane & 7) + ((lane >> 4) & 1) * 8) * SA
                                      + ((lane >> 3) & 1) * 8) * 2;

    const int nk = K >> 5;
    // prologue: tile 0 -> stage 0
    {
        cpasync16(dA,      Ap,     szA);
        cpasync16(dA + 16, Ap + 8, szA);
        cpasync16(dB,      Bp,     16);
        cpasync16(dB + 16, Bp + 8, 16);
        cp_commit();
    }

    for (int it = 0; it < nk; it++){
        const int st = it & 1;
        if (it + 1 < nk){
            const __half* ap = Ap + (it+1)*32;
            const __half* bp = Bp + (it+1)*32;
            const unsigned da = dA + (st^1)*STB;
            const unsigned db = dB + (st^1)*STB;
            cpasync16(da,      ap,     szA);
            cpasync16(da + 16, ap + 8, szA);
            cpasync16(db,      bp,     16);
            cpasync16(db + 16, bp + 8, 16);
        }
        cp_commit();
        cp_wait1();
        __syncthreads();

        const unsigned aBase = sbase + st*STB + laneA;
        const unsigned bBase = sbase + st*STB + MATB + laneB;
        #pragma unroll
        for (int ks = 0; ks < 2; ks++){
            unsigned aR[4][4];
            unsigned bR[4][2];
            #pragma unroll
            for (int mi = 0; mi < 4; mi++)
                ldm4(aR[mi][0], aR[mi][1], aR[mi][2], aR[mi][3],
                     aBase + (unsigned)(((wm + mi*16)*SA + ks*16) * 2));
            #pragma unroll
            for (int p = 0; p < 2; p++)
                ldm4(bR[2*p][0], bR[2*p][1], bR[2*p+1][0], bR[2*p+1][1],
                     bBase + (unsigned)(((wn + p*16)*SA + ks*16) * 2));
            #pragma unroll
            for (int mi = 0; mi < 4; mi++)
                #pragma unroll
                for (int ni = 0; ni < 4; ni++)
                    mma_f16(acc[mi][ni], aR[mi], bR[ni]);
        }
        __syncthreads();
    }

    #pragma unroll
    for (int mi = 0; mi < 4; mi++){
        int r0 = bm + wm + mi*16 + g;
        #pragma unroll
        for (int ni = 0; ni < 4; ni++){
            int c0 = bn + wn + ni*8 + 2*t;
            if (r0 < M){
                *reinterpret_cast<float2*>(C + (size_t)r0*ldc + c0)
                    = make_float2(acc[mi][ni][0], acc[mi][ni][1]);
                if (Ch) *reinterpret_cast<__half2*>(Ch + (size_t)r0*ldc + c0)
                    = __floats2half2_rn(acc[mi][ni][0], acc[mi][ni][1]);
            }
            if (r0 + 8 < M){
                *reinterpret_cast<float2*>(C + (size_t)(r0+8)*ldc + c0)
                    = make_float2(acc[mi][ni][2], acc[mi][ni][3]);
                if (Ch) *reinterpret_cast<__half2*>(Ch + (size_t)(r0+8)*ldc + c0)
                    = __floats2half2_rn(acc[mi][ni][2], acc[mi][ni][3]);
            }
        }
    }
}

// ---------------- layer-1 edge kernel: both heads fused, warp/edge ----------------
__global__ void k_edge1(const int* __restrict__ el, const int* __restrict__ eln,
                        const int* __restrict__ et, const int* __restrict__ etn,
                        const float* __restrict__ sd, const float* __restrict__ ss,
                        const float* __restrict__ sr,
                        const float* __restrict__ Ps, const float* __restrict__ R,
                        float* __restrict__ rs, float* __restrict__ S)
{
    int e = (blockIdx.x * blockDim.x + threadIdx.x) >> 5;
    int lane = threadIdx.x & 31;
    if (e >= ET) return;
    int dst, src, r0, r1 = -1;
    bool onehop = (e < E1);
    if (onehop){
        dst = el[e]; src = el[E1 + e]; r0 = et[e];
    } else {
        int i = e - E1;
        dst = eln[i]; src = eln[EN + i];
        r0 = etn[2*i]; r1 = etn[2*i + 1];
    }
    float ee0, ee1;
    if (lane == 0){
        float sr0 = onehop ? sr[r0]       : (sr[r0]       + sr[r1]);
        float sr1v= onehop ? sr[NREL+r0]  : (sr[NREL+r0]  + sr[NREL+r1]);
        float s0 = sd[dst]      + ss[src]      + sr0;
        float s1 = sd[NN + dst] + ss[NN + src] + sr1v;
        float lk0 = s0 > 0.f ? s0 : 0.2f * s0;
        float lk1 = s1 > 0.f ? s1 : 0.2f * s1;
        ee0 = expf(-lk0);
        ee1 = expf(-lk1);
        atomicAdd(rs + dst, ee0);
        atomicAdd(rs + NN + dst, ee1);
    }
    ee0 = __shfl_sync(0xffffffffu, ee0, 0);
    ee1 = __shfl_sync(0xffffffffu, ee1, 0);
    #pragma unroll
    for (int c0 = 0; c0 < 256; c0 += 128){
        int c = c0 + lane * 4;
        float ee = c0 ? ee1 : ee0;
        float4 p = ld4(Ps + (size_t)src * 256 + c);
        float4 r = ld4(R + (size_t)r0 * 256 + c);
        if (!onehop){
            float4 rb = ld4(R + (size_t)r1 * 256 + c);
            r.x += rb.x; r.y += rb.y; r.z += rb.z; r.w += rb.w;
        }
        red4(S + (size_t)dst * 256 + c,
             make_float4(ee*(p.x+r.x), ee*(p.y+r.y), ee*(p.z+r.z), ee*(p.w+r.w)));
    }
}

// ---------------- layer-2 edge kernel, warp/edge ----------------
__global__ void k_edge2(const int* __restrict__ el, const int* __restrict__ eln,
                        const int* __restrict__ et, const int* __restrict__ etn,
                        const float* __restrict__ sd, const float* __restrict__ ss,
                        const float* __restrict__ sr,
                        const float* __restrict__ Xs, const float* __restrict__ R,
                        float* __restrict__ rs, float* __restrict__ S)
{
    int e = (blockIdx.x * blockDim.x + threadIdx.x) >> 5;
    int lane = threadIdx.x & 31;
    if (e >= ET) return;
    int dst, src, r0, r1 = -1;
    bool onehop = (e < E1);
    if (onehop){
        dst = el[e]; src = el[E1 + e]; r0 = et[e];
    } else {
        int i = e - E1;
        dst = eln[i]; src = eln[EN + i];
        r0 = etn[2*i]; r1 = etn[2*i + 1];
    }
    float ee;
    if (lane == 0){
        float srv = onehop ? sr[r0] : (sr[r0] + sr[r1]);
        float s = sd[dst] + ss[src] + srv;
        float lk = s > 0.f ? s : 0.2f * s;
        ee = expf(-lk);
        atomicAdd(rs + dst, ee);
    }
    ee = __shfl_sync(0xffffffffu, ee, 0);
    #pragma unroll
    for (int c0 = 0; c0 < 256; c0 += 128){
        int c = c0 + lane * 4;
        float4 p = ld4(Xs + (size_t)src * 256 + c);
        float4 r = ld4(R + (size_t)r0 * 256 + c);
        if (!onehop){
            float4 rb = ld4(R + (size_t)r1 * 256 + c);
            r.x += rb.x; r.y += rb.y; r.z += rb.z; r.w += rb.w;
        }
        red4(S + (size_t)dst * 256 + c,
             make_float4(ee*(p.x+r.x), ee*(p.y+r.y), ee*(p.z+r.z), ee*(p.w+r.w)));
    }
}

// ---------------- layer-1 finalize -> x (fp16) ----------------
__global__ void k_fin1(const float* __restrict__ Pd, const float* __restrict__ S,
                       const float* __restrict__ rs, __half* __restrict__ x)
{
    int n = (blockIdx.x * blockDim.x + threadIdx.x) >> 5;
    int lane = threadIdx.x & 31;
    if (n >= NN) return;
    int c = lane * 4;
    #pragma unroll
    for (int h = 0; h < 2; h++){
        float r  = rs[h*NN + n];
        float rc = (r == 0.f) ? 1e-12f : r;
        float4 pd = ld4(Pd + (size_t)n*512 + h*128 + c);
        float4 s  = ld4(S  + (size_t)n*256 + h*128 + c);
        float h0 = elu1(fmaf(r, pd.x, s.x) / rc);
        float h1 = elu1(fmaf(r, pd.y, s.y) / rc);
        float h2 = elu1(fmaf(r, pd.z, s.z) / rc);
        float h3 = elu1(fmaf(r, pd.w, s.w) / rc);
        __half* xp = x + (size_t)n*256 + h*128 + c;
        *reinterpret_cast<__half2*>(xp)     = __floats2half2_rn(h0, h1);
        *reinterpret_cast<__half2*>(xp + 2) = __floats2half2_rn(h2, h3);
    }
}

// ---------------- final outputs ----------------
__global__ void k_final(const float* __restrict__ Pd /*eup at +256*/,
                        const float* __restrict__ Xd,
                        const float* __restrict__ S2, const float* __restrict__ rs2,
                        const float* __restrict__ mask,
                        float* __restrict__ out1, float* __restrict__ out3)
{
    int n = (blockIdx.x * blockDim.x + threadIdx.x) >> 5;
    int lane = threadIdx.x & 31;
    if (n >= NN) return;
    float r  = rs2[n];
    float rc = (r == 0.f) ? 1e-12f : r;
    float mk = mask[n];
    float4 v1[2], v3[2];
    float ss1 = 0.f, ss3 = 0.f;
    #pragma unroll
    for (int q = 0; q < 2; q++){
        int c = q*128 + lane*4;
        float4 xd = ld4(Xd + (size_t)n*256 + c);
        float4 s2 = ld4(S2 + (size_t)n*256 + c);
        float4 e4 = ld4(Pd + (size_t)n*512 + 256 + c);
        float hr0 = fmaf(r, xd.x, s2.x);
        float hr1 = fmaf(r, xd.y, s2.y);
        float hr2 = fmaf(r, xd.z, s2.z);
        float hr3 = fmaf(r, xd.w, s2.w);
        float a0 = e4.x + mk * elu1(hr0 / rc);
        float a1 = e4.y + mk * elu1(hr1 / rc);
        float a2 = e4.z + mk * elu1(hr2 / rc);
        float a3 = e4.w + mk * elu1(hr3 / rc);
        float b0 = elu1(hr0), b1 = elu1(hr1), b2 = elu1(hr2), b3 = elu1(hr3);
        v1[q] = make_float4(a0, a1, a2, a3);
        v3[q] = make_float4(b0, b1, b2, b3);
        ss1 += a0*a0 + a1*a1 + a2*a2 + a3*a3;
        ss3 += b0*b0 + b1*b1 + b2*b2 + b3*b3;
    }
    ss1 = wred(ss1);
    ss3 = wred(ss3);
    float sc1 = 1.f / fmaxf(sqrtf(ss1), 1e-12f);
    float sc3 = 1.f / fmaxf(sqrtf(ss3), 1e-12f);
    #pragma unroll
    for (int q = 0; q < 2; q++){
        int c = q*128 + lane*4;
        st4(out1 + (size_t)n*256 + c, make_float4(v1[q].x*sc1, v1[q].y*sc1, v1[q].z*sc1, v1[q].w*sc1));
        st4(out3 + (size_t)n*256 + c, make_float4(v3[q].x*sc3, v3[q].y*sc3, v3[q].z*sc3, v3[q].w*sc3));
    }
}

// ---------------- host launch ----------------
static void* symv(const void* s){
    void* p = nullptr;
    cudaGetSymbolAddress(&p, s);
    return p;
}

extern "C" void kernel_launch(void* const* d_in, const int* in_sizes, int n_in,
                              void* d_out, int out_size)
{
    const float* ent    = (const float*)d_in[0];
    const float* rel    = (const float*)d_in[1];
    const float* a1     = (const float*)d_in[2];
    const float* a2_1   = (const float*)d_in[3];
    const float* W      = (const float*)d_in[4];
    const float* a_out  = (const float*)d_in[5];
    const float* a2_out = (const float*)d_in[6];
    const float* W_ent  = (const float*)d_in[7];
    const int*   bi     = (const int*)d_in[8];
    const int*   el     = (const int*)d_in[9];
    const int*   et     = (const int*)d_in[10];
    const int*   eln    = (const int*)d_in[11];
    const int*   etn    = (const int*)d_in[12];
    float* out = (float*)d_out;

    float* Z      = (float*)symv(g_Z);
    float* p_S1   = Z + OFF_S1;
    float* p_S2   = Z + OFF_S2;
    float* p_rs1  = Z + OFF_RS1;
    float* p_rs2  = Z + OFF_RS2;
    float* p_mask = Z + OFF_MASK;
    __half* entH  = (__half*)symv(g_entH);
    __half* xH    = (__half*)symv(g_xH);
    __half* orelH = (__half*)symv(g_orelH);
    float* p_Pd = (float*)symv(g_Pd);  float* p_Ps = (float*)symv(g_Ps);
    float* p_R1 = (float*)symv(g_R1);  float* p_Xd = (float*)symv(g_Xd);
    float* p_Xs = (float*)symv(g_Xs);  float* p_R2 = (float*)symv(g_R2);
    float* p_sd1= (float*)symv(g_sd1); float* p_ss1= (float*)symv(g_ss1);
    float* p_sr1= (float*)symv(g_sr1); float* p_sd2= (float*)symv(g_sd2);
    float* p_ss2= (float*)symv(g_ss2); float* p_sr2= (float*)symv(g_sr2);
    __half* B1d = (__half*)symv(hB1d); __half* B1s = (__half*)symv(hB1s);
    __half* BR1 = (__half*)symv(hBR1); __half* B2d = (__half*)symv(hB2d);
    __half* B2s = (__half*)symv(hB2s); __half* B3  = (__half*)symv(hB3);
    __half* BW  = (__half*)symv(hBW);  __half* relH= (__half*)symv(g_relH);

    const int T = 256;
    const int GY = (NN + 127) / 128;
    const int GW = (NN*32 + T - 1) / T;
    const int GE = (ET*32 + T - 1) / T;
    const int NPACK = 512*128 + 2*256*128 + 3*256*256 + 2*256*128;

    // 1: zero scratch
    k_zero4<<<4096, T>>>((float4*)Z, ZN/4);
    // 2: pack fp16 weights + relH
    k_packs<<<(NPACK + T-1)/T, T>>>(a1, a_out, W, W_ent, rel,
                                    B1d, B1s, BR1, B2d, B2s, B3, BW, relH);
    // 3: l2 normalize entities -> fp16
    k_l2norm128<<<GW, T>>>(ent, entH);
    // 4: big layer-1 dst/eup GEMM  (profiled launch)
    gemm_tn_f16<<<dim3(4, GY), T>>>(entH, 128, B1d, 128, p_Pd, 512, nullptr, NN, 512, 128);
    // 5: Ps GEMM
    gemm_tn_f16<<<dim3(2, GY), T>>>(entH, 128, B1s, 128, p_Ps, 256, nullptr, NN, 256, 128);
    // 6: relation projections (both heads)
    gemm_tn_f16<<<dim3(2, 2), T>>>(relH, 128, BR1, 128, p_R1, 256, nullptr, NREL, 256, 128);
    // 7: attention scalars (node side)
    k_dots1<<<GW, T>>>(p_Pd, p_Ps, a2_1, p_sd1, p_ss1);
    // 8-9: attention scalars (relation side)
    k_rowdot<<<(NREL*32 + T-1)/T, T>>>(p_R1,       256, 128, a2_1,       p_sr1,        NREL);
    k_rowdot<<<(NREL*32 + T-1)/T, T>>>(p_R1 + 128, 256, 128, a2_1 + 128, p_sr1 + NREL, NREL);
    // 10: fused 2-head edge scatter
    k_edge1<<<GE, T>>>(el, eln, et, etn, p_sd1, p_ss1, p_sr1, p_Ps, p_R1, p_rs1, p_S1);
    // 11: layer-1 finalize -> xH
    k_fin1<<<GW, T>>>(p_Pd, p_S1, p_rs1, xH);
    // 12: out_relation_1 = rel @ W (fp32 out + fp16 copy)
    gemm_tn_f16<<<dim3(2, 2), T>>>(relH, 128, BW, 128, out + OREL, 256, orelH, NREL, 256, 128);
    // 13-14: layer-2 node projections
    gemm_tn_f16<<<dim3(2, GY), T>>>(xH, 256, B2d, 256, p_Xd, 256, nullptr, NN, 256, 256);
    gemm_tn_f16<<<dim3(2, GY), T>>>(xH, 256, B2s, 256, p_Xs, 256, nullptr, NN, 256, 256);
    // 15: layer-2 relation projection
    gemm_tn_f16<<<dim3(2, 2), T>>>(orelH, 256, B3, 256, p_R2, 256, nullptr, NREL, 256, 256);
    // 16: layer-2 attention scalars
    k_dots2<<<GW, T>>>(p_Xd, p_Xs, a2_out, p_sd2, p_ss2);
    // 17: relation-side scalar
    k_rowdot<<<(NREL*32 + T-1)/T, T>>>(p_R2, 256, 256, a2_out, p_sr2, NREL);
    // 18: mask scatter
    k_setmask<<<16, T>>>(bi, p_mask);
    // 19: layer-2 edge scatter
    k_edge2<<<GE, T>>>(el, eln, et, etn, p_sd2, p_ss2, p_sr2, p_Xs, p_R2, p_rs2, p_S2);
    // 20: final outputs
    k_final<<<GW, T>>>(p_Pd, p_Xd, p_S2, p_rs2, p_mask, out, out + O3);
}